// round 5
// baseline (speedup 1.0000x reference)
#include <cuda_runtime.h>
#include <cuda_fp16.h>
#include <stdint.h>
#include <math.h>

#define N_TOK 2048
#define C_DIM 1024
#define NHEAD 8
#define HD    128
#define NGRP  32
#define HW    64
#define PAD   40   // smem row stride in halfs (80B, multiple of 16B, conflict-free)

// ---------------- scratch (device globals: allocation-free) ----------------
__device__ float g_feat[N_TOK * C_DIM];
__device__ float g_qkv [N_TOK * 3 * C_DIM];
__device__ float g_coef[N_TOK * C_DIM];
__device__ int   g_bidx[N_TOK];
__device__ int   g_cnt [NGRP];
__device__ int   g_list[NGRP * N_TOK];
__device__ __half g_fh [N_TOK * C_DIM], g_fl [N_TOK * C_DIM];
__device__ __half g_wq [3 * C_DIM * C_DIM];
__device__ __half g_wo [C_DIM * C_DIM];
__device__ __half g_ah [N_TOK * C_DIM], g_al [N_TOK * C_DIM];

__device__ __forceinline__ uint32_t smem_u32(const void* p) {
    uint32_t a;
    asm("{ .reg .u64 t; cvta.to.shared.u64 t, %1; cvt.u32.u64 %0, t; }" : "=r"(a) : "l"(p));
    return a;
}
__device__ __forceinline__ void cp16(uint32_t dst, const void* src) {
    asm volatile("cp.async.cg.shared.global [%0], [%1], 16;" :: "r"(dst), "l"(src));
}

// ---------------- 1) groups: detect width, lists + counts ------------------
__global__ void k_groups(const int* __restrict__ raw) {
    __shared__ int sb[N_TOK];
    __shared__ int s64;
    if (threadIdx.x == 0) {
        int acc = 0;
        #pragma unroll
        for (int i = 0; i < 32; i++) acc |= raw[2 * i + 1];
        s64 = (acc == 0);
    }
    __syncthreads();
    for (int i = threadIdx.x; i < N_TOK; i += blockDim.x)
        sb[i] = s64 ? raw[2 * i] : raw[i];
    __syncthreads();
    int i = blockIdx.x * blockDim.x + threadIdx.x;   // grid 8 x 256
    if (blockIdx.x == 0) {
        for (int j = threadIdx.x; j < N_TOK; j += blockDim.x) g_bidx[j] = sb[j];
    }
    int b = sb[i];
    int pos = 0;
    for (int j = 0; j < i; j++) pos += (sb[j] == b) ? 1 : 0;
    g_list[b * N_TOK + pos] = i;
    if (blockIdx.x == 0 && threadIdx.x < NGRP) {
        int c = 0;
        for (int j = 0; j < N_TOK; j++) c += (sb[j] == (int)threadIdx.x) ? 1 : 0;
        g_cnt[threadIdx.x] = c;
    }
}

// ---------------- 2) feat = mean over H*W (2 threads/row, MLP=8) -----------
__global__ void k_mean(const float* __restrict__ x) {
    const int TOTAL = N_TOK * C_DIM * 2;          // pair slots
    int gsize = gridDim.x * blockDim.x;
    for (int p = blockIdx.x * blockDim.x + threadIdx.x; p < TOTAL; p += gsize) {
        int row = p >> 1, half = p & 1;
        const float4* b = (const float4*)x + (size_t)row * 16 + half * 8;
        float4 v0 = __ldcs(b + 0), v1 = __ldcs(b + 1), v2 = __ldcs(b + 2), v3 = __ldcs(b + 3);
        float4 v4 = __ldcs(b + 4), v5 = __ldcs(b + 5), v6 = __ldcs(b + 6), v7 = __ldcs(b + 7);
        float s = ((v0.x + v0.y) + (v0.z + v0.w)) + ((v1.x + v1.y) + (v1.z + v1.w))
                + ((v2.x + v2.y) + (v2.z + v2.w)) + ((v3.x + v3.y) + (v3.z + v3.w))
                + ((v4.x + v4.y) + (v4.z + v4.w)) + ((v5.x + v5.y) + (v5.z + v5.w))
                + ((v6.x + v6.y) + (v6.z + v6.w)) + ((v7.x + v7.y) + (v7.z + v7.w));
        s += __shfl_xor_sync(0xffffffffu, s, 1);
        if (!half) g_feat[row] = s * (1.0f / 64.0f);
    }
}

// ---------------- 3) LayerNorm over C, emit fp16 hi/lo ---------------------
__global__ void k_ln(const float* __restrict__ w, const float* __restrict__ b) {
    int row = blockIdx.x, tid = threadIdx.x;
    int lane = tid & 31, warp = tid >> 5;
    float4 v = ((const float4*)g_feat)[row * 256 + tid];
    float s  = v.x + v.y + v.z + v.w;
    float sq = v.x * v.x + v.y * v.y + v.z * v.z + v.w * v.w;
    #pragma unroll
    for (int off = 16; off; off >>= 1) {
        s  += __shfl_xor_sync(0xffffffffu, s,  off);
        sq += __shfl_xor_sync(0xffffffffu, sq, off);
    }
    __shared__ float rs[8], rq[8];
    if (lane == 0) { rs[warp] = s; rq[warp] = sq; }
    __syncthreads();
    float S = 0.f, SQ = 0.f;
    #pragma unroll
    for (int i = 0; i < 8; i++) { S += rs[i]; SQ += rq[i]; }
    float mu   = S * (1.0f / C_DIM);
    float var  = SQ * (1.0f / C_DIM) - mu * mu;
    float rstd = rsqrtf(var + 1e-5f);
    float4 wv = ((const float4*)w)[tid], bv = ((const float4*)b)[tid];
    float a[4];
    a[0] = (v.x - mu) * rstd * wv.x + bv.x;
    a[1] = (v.y - mu) * rstd * wv.y + bv.y;
    a[2] = (v.z - mu) * rstd * wv.z + bv.z;
    a[3] = (v.w - mu) * rstd * wv.w + bv.w;
    __half hs[4], ls[4];
    #pragma unroll
    for (int j = 0; j < 4; j++) {
        hs[j] = __float2half_rn(a[j]);
        ls[j] = __float2half_rn(a[j] - __half2float(hs[j]));
    }
    *(uint2*)&g_fh[row * C_DIM + tid * 4] = *(uint2*)hs;
    *(uint2*)&g_fl[row * C_DIM + tid * 4] = *(uint2*)ls;
}

// ---------------- 3b) fp32 -> fp16 (weights) -------------------------------
__global__ void k_half(const float* __restrict__ src, __half* __restrict__ dst, int n4) {
    int i = blockIdx.x * blockDim.x + threadIdx.x;
    if (i >= n4) return;
    float4 v = __ldcs(&((const float4*)src)[i]);
    __half hs[4] = { __float2half_rn(v.x), __float2half_rn(v.y),
                     __float2half_rn(v.z), __float2half_rn(v.w) };
    *(uint2*)&dst[i * 4] = *(uint2*)hs;
}

// ---------------- 4) HMMA GEMM, cp.async 2-stage pipeline ------------------
// C[M,N] = (Ah+Al)[M,K] * B[N,K]^T + bias. Block 128x128, 8 warps, k-chunk 32.
#define STG_BYTES (128 * PAD * 2)
__global__ void __launch_bounds__(256)
k_hgemm(const __half* __restrict__ Ah, const __half* __restrict__ Al,
        const __half* __restrict__ B, const float* __restrict__ bias,
        float* __restrict__ C, int Ncols, int mode, const float* __restrict__ gamma) {
    extern __shared__ __half sm[];
    const uint32_t base = smem_u32(sm);
    const uint32_t oAh = 0, oAl = 2 * STG_BYTES, oB = 4 * STG_BYTES;

    const int tid = threadIdx.x, warp = tid >> 5, lane = tid & 31;
    const int wm = warp >> 2, wn = warp & 3;
    const int bM = blockIdx.y * 128, bN = blockIdx.x * 128;

    float acc[4][4][4];
    #pragma unroll
    for (int i = 0; i < 4; i++)
        #pragma unroll
        for (int j = 0; j < 4; j++)
            #pragma unroll
            for (int c = 0; c < 4; c++) acc[i][j][c] = 0.f;

    const int lr0 = tid >> 2, lc0 = (tid & 3) * 8;
    const int lr1 = (tid + 256) >> 2, lc1 = ((tid + 256) & 3) * 8;

    const int a_row = lane & 15, a_k = (lane >> 4) * 8;
    const int b_row = (lane & 7) + ((lane >> 4) << 3);
    const int b_k   = ((lane >> 3) & 1) * 8;

    // ---- stage loader ----
    #define LOAD_STAGE(kc, st) do {                                              \
        uint32_t so = (st) * STG_BYTES;                                          \
        size_t ga0 = (size_t)(bM + lr0) * C_DIM + (kc) * 32 + lc0;               \
        size_t ga1 = (size_t)(bM + lr1) * C_DIM + (kc) * 32 + lc1;               \
        size_t gb0 = (size_t)(bN + lr0) * C_DIM + (kc) * 32 + lc0;               \
        size_t gb1 = (size_t)(bN + lr1) * C_DIM + (kc) * 32 + lc1;               \
        cp16(base + oAh + so + (lr0 * PAD + lc0) * 2, Ah + ga0);                 \
        cp16(base + oAh + so + (lr1 * PAD + lc1) * 2, Ah + ga1);                 \
        cp16(base + oAl + so + (lr0 * PAD + lc0) * 2, Al + ga0);                 \
        cp16(base + oAl + so + (lr1 * PAD + lc1) * 2, Al + ga1);                 \
        cp16(base + oB  + so + (lr0 * PAD + lc0) * 2, B + gb0);                  \
        cp16(base + oB  + so + (lr1 * PAD + lc1) * 2, B + gb1);                  \
        asm volatile("cp.async.commit_group;");                                  \
    } while (0)

    LOAD_STAGE(0, 0);

    for (int kc = 0; kc < 32; kc++) {
        int cur = kc & 1;
        if (kc < 31) {
            LOAD_STAGE(kc + 1, cur ^ 1);
            asm volatile("cp.async.wait_group 1;");
        } else {
            asm volatile("cp.async.wait_group 0;");
        }
        __syncthreads();

        uint32_t so = cur * STG_BYTES;
        #pragma unroll
        for (int ks = 0; ks < 32; ks += 16) {
            uint32_t aH[4][4], aL[4][4], bF[4][2];
            #pragma unroll
            for (int i = 0; i < 4; i++) {
                uint32_t off = so + (uint32_t)((wm * 64 + i * 16 + a_row) * PAD + ks + a_k) * 2;
                asm volatile("ldmatrix.sync.aligned.m8n8.x4.shared.b16 {%0,%1,%2,%3}, [%4];"
                    : "=r"(aH[i][0]), "=r"(aH[i][1]), "=r"(aH[i][2]), "=r"(aH[i][3])
                    : "r"(base + oAh + off));
                asm volatile("ldmatrix.sync.aligned.m8n8.x4.shared.b16 {%0,%1,%2,%3}, [%4];"
                    : "=r"(aL[i][0]), "=r"(aL[i][1]), "=r"(aL[i][2]), "=r"(aL[i][3])
                    : "r"(base + oAl + off));
            }
            #pragma unroll
            for (int jj = 0; jj < 2; jj++) {
                uint32_t off = so + (uint32_t)((wn * 32 + jj * 16 + b_row) * PAD + ks + b_k) * 2;
                uint32_t r0, r1, r2, r3;
                asm volatile("ldmatrix.sync.aligned.m8n8.x4.shared.b16 {%0,%1,%2,%3}, [%4];"
                    : "=r"(r0), "=r"(r1), "=r"(r2), "=r"(r3) : "r"(base + oB + off));
                bF[jj * 2 + 0][0] = r0; bF[jj * 2 + 0][1] = r1;
                bF[jj * 2 + 1][0] = r2; bF[jj * 2 + 1][1] = r3;
            }
            #pragma unroll
            for (int i = 0; i < 4; i++)
                #pragma unroll
                for (int j = 0; j < 4; j++) {
                    asm volatile(
                        "mma.sync.aligned.m16n8k16.row.col.f32.f16.f16.f32 "
                        "{%0,%1,%2,%3}, {%4,%5,%6,%7}, {%8,%9}, {%0,%1,%2,%3};"
                        : "+f"(acc[i][j][0]), "+f"(acc[i][j][1]),
                          "+f"(acc[i][j][2]), "+f"(acc[i][j][3])
                        : "r"(aH[i][0]), "r"(aH[i][1]), "r"(aH[i][2]), "r"(aH[i][3]),
                          "r"(bF[j][0]), "r"(bF[j][1]));
                    asm volatile(
                        "mma.sync.aligned.m16n8k16.row.col.f32.f16.f16.f32 "
                        "{%0,%1,%2,%3}, {%4,%5,%6,%7}, {%8,%9}, {%0,%1,%2,%3};"
                        : "+f"(acc[i][j][0]), "+f"(acc[i][j][1]),
                          "+f"(acc[i][j][2]), "+f"(acc[i][j][3])
                        : "r"(aL[i][0]), "r"(aL[i][1]), "r"(aL[i][2]), "r"(aL[i][3]),
                          "r"(bF[j][0]), "r"(bF[j][1]));
                }
        }
        __syncthreads();
    }

    const int g4 = lane >> 2, t4 = lane & 3;
    #pragma unroll
    for (int i = 0; i < 4; i++) {
        int r0 = bM + wm * 64 + i * 16 + g4;
        int r1 = r0 + 8;
        float gm0 = 1.f, gm1 = 1.f;
        if (mode == 1) {
            gm0 = (g_cnt[g_bidx[r0]] > 1) ? gamma[0] : 0.0f;
            gm1 = (g_cnt[g_bidx[r1]] > 1) ? gamma[0] : 0.0f;
        }
        #pragma unroll
        for (int j = 0; j < 4; j++) {
            int c = bN + wn * 32 + j * 8 + 2 * t4;
            float b0 = bias[c], b1 = bias[c + 1];
            float2 o0 = { (acc[i][j][0] + b0) * gm0, (acc[i][j][1] + b1) * gm0 };
            float2 o1 = { (acc[i][j][2] + b0) * gm1, (acc[i][j][3] + b1) * gm1 };
            *(float2*)&C[(size_t)r0 * Ncols + c] = o0;
            *(float2*)&C[(size_t)r1 * Ncols + c] = o1;
        }
    }
}

// ---------------- 5) per-(head,group) flash attention ----------------------
__global__ void k_attn() {
    int bx = blockIdx.x;               // 256 blocks: h*NGRP + g
    int g  = bx & (NGRP - 1);
    int h  = bx >> 5;
    int m  = g_cnt[g];
    int tid = threadIdx.x, w = tid >> 5, lane = tid & 31;
    __shared__ float Ks[32][HD];
    __shared__ float Vs[32][HD];

    for (int q0 = 0; q0 < m; q0 += 64) {
        float q[8][4], acc[8][4], mx[8], l[8];
        int   tok[8];
        #pragma unroll
        for (int t = 0; t < 8; t++) {
            int qi = q0 + w * 8 + t;
            if (qi < m) {
                tok[t] = g_list[g * N_TOK + qi];
                float4 qv = *(const float4*)&g_qkv[(size_t)tok[t] * 3072 + h * HD + lane * 4];
                q[t][0] = qv.x; q[t][1] = qv.y; q[t][2] = qv.z; q[t][3] = qv.w;
            } else tok[t] = -1;
            mx[t] = -1e30f; l[t] = 0.f;
            acc[t][0] = acc[t][1] = acc[t][2] = acc[t][3] = 0.f;
        }

        int ntile = (m + 31) >> 5;
        for (int kt = 0; kt < ntile; kt++) {
            int kbase = kt * 32;
            #pragma unroll
            for (int it = 0; it < 4; it++) {
                int p  = tid + it * 256;
                int j  = p >> 5, c4 = p & 31;
                int kj = kbase + j;
                float4 kv = {0,0,0,0}, vv = {0,0,0,0};
                if (kj < m) {
                    int ktok = g_list[g * N_TOK + kj];
                    const float4* b4 = (const float4*)&g_qkv[(size_t)ktok * 3072];
                    kv = b4[256 + h * 32 + c4];
                    vv = b4[512 + h * 32 + c4];
                }
                *(float4*)&Ks[j][c4 * 4] = kv;
                *(float4*)&Vs[j][c4 * 4] = vv;
            }
            __syncthreads();

            int jmax = m - kbase; if (jmax > 32) jmax = 32;
            for (int j = 0; j < jmax; j++) {
                float4 kj4 = *(const float4*)&Ks[j][lane * 4];
                float4 vj4 = *(const float4*)&Vs[j][lane * 4];
                #pragma unroll
                for (int t = 0; t < 8; t++) {
                    if (tok[t] < 0) continue;
                    float s = q[t][0] * kj4.x + q[t][1] * kj4.y
                            + q[t][2] * kj4.z + q[t][3] * kj4.w;
                    #pragma unroll
                    for (int off = 16; off; off >>= 1) s += __shfl_xor_sync(0xffffffffu, s, off);
                    s *= 0.08838834764831845f;
                    if (s <= mx[t]) {
                        float p = __expf(s - mx[t]);
                        l[t] += p;
                        acc[t][0] += p * vj4.x; acc[t][1] += p * vj4.y;
                        acc[t][2] += p * vj4.z; acc[t][3] += p * vj4.w;
                    } else {
                        float corr = __expf(mx[t] - s);
                        l[t] = l[t] * corr + 1.0f;
                        acc[t][0] = acc[t][0] * corr + vj4.x;
                        acc[t][1] = acc[t][1] * corr + vj4.y;
                        acc[t][2] = acc[t][2] * corr + vj4.z;
                        acc[t][3] = acc[t][3] * corr + vj4.w;
                        mx[t] = s;
                    }
                }
            }
            __syncthreads();
        }

        #pragma unroll
        for (int t = 0; t < 8; t++) {
            if (tok[t] < 0) continue;
            float inv = 1.0f / l[t];
            float a[4] = { acc[t][0] * inv, acc[t][1] * inv, acc[t][2] * inv, acc[t][3] * inv };
            __half hs[4], ls[4];
            #pragma unroll
            for (int j = 0; j < 4; j++) {
                hs[j] = __float2half_rn(a[j]);
                ls[j] = __float2half_rn(a[j] - __half2float(hs[j]));
            }
            size_t idx = (size_t)tok[t] * C_DIM + h * HD + lane * 4;
            *(uint2*)&g_ah[idx] = *(uint2*)hs;
            *(uint2*)&g_al[idx] = *(uint2*)ls;
        }
    }
}

// ---------------- 6) y = x + coef[n,c], streaming, MLP=8 -------------------
__global__ void k_add(const float* __restrict__ x, float* __restrict__ y) {
    const float4* x4 = (const float4*)x;
    float4* y4 = (float4*)y;
    const int TOTALU = N_TOK * C_DIM * 2;       // half-row units of 8 float4
    int gsize = gridDim.x * blockDim.x;
    for (int u = blockIdx.x * blockDim.x + threadIdx.x; u < TOTALU; u += gsize) {
        float c = g_coef[u >> 1];
        const float4* xb = x4 + (size_t)u * 8;
        float4* yb = y4 + (size_t)u * 8;
        float4 v[8];
        #pragma unroll
        for (int j = 0; j < 8; j++) v[j] = __ldcs(xb + j);
        #pragma unroll
        for (int j = 0; j < 8; j++) {
            v[j].x += c; v[j].y += c; v[j].z += c; v[j].w += c;
            __stcs(yb + j, v[j]);
        }
    }
}

// ---------------- launch ---------------------------------------------------
extern "C" void kernel_launch(void* const* d_in, const int* in_sizes, int n_in,
                              void* d_out, int out_size) {
    const float* x          = (const float*)d_in[0];
    const int*   braw       = (const int*)  d_in[1];
    const float* ln_w       = (const float*)d_in[2];
    const float* ln_b       = (const float*)d_in[3];
    const float* in_proj_w  = (const float*)d_in[4];
    const float* in_proj_b  = (const float*)d_in[5];
    const float* out_proj_w = (const float*)d_in[6];
    const float* out_proj_b = (const float*)d_in[7];
    const float* gamma      = (const float*)d_in[8];
    float* y = (float*)d_out;

    __half *p_fh, *p_fl, *p_wq, *p_wo, *p_ah, *p_al;
    float *p_qkv, *p_coef;
    cudaGetSymbolAddress((void**)&p_fh,  g_fh);
    cudaGetSymbolAddress((void**)&p_fl,  g_fl);
    cudaGetSymbolAddress((void**)&p_wq,  g_wq);
    cudaGetSymbolAddress((void**)&p_wo,  g_wo);
    cudaGetSymbolAddress((void**)&p_ah,  g_ah);
    cudaGetSymbolAddress((void**)&p_al,  g_al);
    cudaGetSymbolAddress((void**)&p_qkv, g_qkv);
    cudaGetSymbolAddress((void**)&p_coef, g_coef);

    const int GSM = 6 * STG_BYTES;   // 61440 B
    cudaFuncSetAttribute(k_hgemm, cudaFuncAttributeMaxDynamicSharedMemorySize, GSM);

    k_groups <<<8, 256>>>(braw);
    k_mean   <<<1184, 256>>>(x);
    k_ln     <<<N_TOK, 256>>>(ln_w, ln_b);
    k_half   <<<3072, 256>>>(in_proj_w,  p_wq, 3 * C_DIM * C_DIM / 4);
    k_half   <<<1024, 256>>>(out_proj_w, p_wo, C_DIM * C_DIM / 4);
    k_hgemm  <<<dim3(24, 16), 256, GSM>>>(p_fh, p_fl, p_wq, in_proj_b, p_qkv,
                                          3 * C_DIM, 0, nullptr);
    k_attn   <<<NHEAD * NGRP, 256>>>();
    k_hgemm  <<<dim3(8, 16), 256, GSM>>>(p_ah, p_al, p_wo, out_proj_b, p_coef,
                                         C_DIM, 1, gamma);
    k_add    <<<1184, 256>>>(x, y);
}

// round 6
// speedup vs baseline: 1.2150x; 1.2150x over previous
#include <cuda_runtime.h>
#include <cuda_fp16.h>
#include <stdint.h>
#include <math.h>

#define N_TOK 2048
#define C_DIM 1024
#define NHEAD 8
#define HD    128
#define NGRP  32
#define HW    64
#define PAD   40   // smem row stride in halfs (80B, multiple of 16B, conflict-free)

// ---------------- scratch (device globals: allocation-free) ----------------
__device__ float g_feat[N_TOK * C_DIM];
__device__ float g_qkv [N_TOK * 3 * C_DIM];
__device__ float g_coef[N_TOK * C_DIM];
__device__ int   g_bidx[N_TOK];
__device__ int   g_cnt [NGRP];
__device__ int   g_list[NGRP * N_TOK];
__device__ __half g_fh [N_TOK * C_DIM], g_fl [N_TOK * C_DIM];
__device__ __half g_wq [3 * C_DIM * C_DIM];
__device__ __half g_wo [C_DIM * C_DIM];
__device__ __half g_ah [N_TOK * C_DIM], g_al [N_TOK * C_DIM];

__device__ __forceinline__ uint32_t smem_u32(const void* p) {
    uint32_t a;
    asm("{ .reg .u64 t; cvta.to.shared.u64 t, %1; cvt.u32.u64 %0, t; }" : "=r"(a) : "l"(p));
    return a;
}

// ---------------- 1) groups: detect width, lists + counts ------------------
__global__ void k_groups(const int* __restrict__ raw) {
    __shared__ int sb[N_TOK];
    __shared__ int s64;
    if (threadIdx.x == 0) {
        int acc = 0;
        #pragma unroll
        for (int i = 0; i < 32; i++) acc |= raw[2 * i + 1];
        s64 = (acc == 0);
    }
    __syncthreads();
    for (int i = threadIdx.x; i < N_TOK; i += blockDim.x)
        sb[i] = s64 ? raw[2 * i] : raw[i];
    __syncthreads();
    int i = blockIdx.x * blockDim.x + threadIdx.x;   // grid 8 x 256
    if (blockIdx.x == 0) {
        for (int j = threadIdx.x; j < N_TOK; j += blockDim.x) g_bidx[j] = sb[j];
    }
    int b = sb[i];
    int pos = 0;
    for (int j = 0; j < i; j++) pos += (sb[j] == b) ? 1 : 0;
    g_list[b * N_TOK + pos] = i;
    if (blockIdx.x == 0 && threadIdx.x < NGRP) {
        int c = 0;
        for (int j = 0; j < N_TOK; j++) c += (sb[j] == (int)threadIdx.x) ? 1 : 0;
        g_cnt[threadIdx.x] = c;
    }
}

// ---------------- 2) feat = mean over H*W -----------------------------------
// Warp handles a 4KB chunk (16 rows) via 8 independent, lane-coalesced LDG.128.
__global__ void k_mean(const float* __restrict__ x) {
    const float4* x4 = (const float4*)x;
    int gw    = (blockIdx.x * blockDim.x + threadIdx.x) >> 5;
    int lane  = threadIdx.x & 31;
    int nwarp = (gridDim.x * blockDim.x) >> 5;
    const int CHUNKS = N_TOK * C_DIM / 16;        // 131072 chunks of 16 rows
    for (int ch = gw; ch < CHUNKS; ch += nwarp) {
        size_t base = (size_t)ch * 256 + lane;
        float4 v[8];
        #pragma unroll
        for (int j = 0; j < 8; j++) v[j] = __ldcs(&x4[base + 32 * j]);
        float s[8];
        #pragma unroll
        for (int j = 0; j < 8; j++) s[j] = (v[j].x + v[j].y) + (v[j].z + v[j].w);
        #pragma unroll
        for (int j = 0; j < 8; j++) {
            s[j] += __shfl_xor_sync(0xffffffffu, s[j], 8);
            s[j] += __shfl_xor_sync(0xffffffffu, s[j], 4);
            s[j] += __shfl_xor_sync(0xffffffffu, s[j], 2);
            s[j] += __shfl_xor_sync(0xffffffffu, s[j], 1);
        }
        if (lane == 0 || lane == 16) {
            int r0 = ch * 16 + (lane >> 4);
            #pragma unroll
            for (int j = 0; j < 8; j++) g_feat[r0 + 2 * j] = s[j] * (1.0f / 64.0f);
        }
    }
}

// ---------------- 3) LayerNorm over C, emit fp16 hi/lo ---------------------
__global__ void k_ln(const float* __restrict__ w, const float* __restrict__ b) {
    int row = blockIdx.x, tid = threadIdx.x;
    int lane = tid & 31, warp = tid >> 5;
    float4 v = ((const float4*)g_feat)[row * 256 + tid];
    float s  = v.x + v.y + v.z + v.w;
    float sq = v.x * v.x + v.y * v.y + v.z * v.z + v.w * v.w;
    #pragma unroll
    for (int off = 16; off; off >>= 1) {
        s  += __shfl_xor_sync(0xffffffffu, s,  off);
        sq += __shfl_xor_sync(0xffffffffu, sq, off);
    }
    __shared__ float rs[8], rq[8];
    if (lane == 0) { rs[warp] = s; rq[warp] = sq; }
    __syncthreads();
    float S = 0.f, SQ = 0.f;
    #pragma unroll
    for (int i = 0; i < 8; i++) { S += rs[i]; SQ += rq[i]; }
    float mu   = S * (1.0f / C_DIM);
    float var  = SQ * (1.0f / C_DIM) - mu * mu;
    float rstd = rsqrtf(var + 1e-5f);
    float4 wv = ((const float4*)w)[tid], bv = ((const float4*)b)[tid];
    float a[4];
    a[0] = (v.x - mu) * rstd * wv.x + bv.x;
    a[1] = (v.y - mu) * rstd * wv.y + bv.y;
    a[2] = (v.z - mu) * rstd * wv.z + bv.z;
    a[3] = (v.w - mu) * rstd * wv.w + bv.w;
    __half hs[4], ls[4];
    #pragma unroll
    for (int j = 0; j < 4; j++) {
        hs[j] = __float2half_rn(a[j]);
        ls[j] = __float2half_rn(a[j] - __half2float(hs[j]));
    }
    *(uint2*)&g_fh[row * C_DIM + tid * 4] = *(uint2*)hs;
    *(uint2*)&g_fl[row * C_DIM + tid * 4] = *(uint2*)ls;
}

// ---------------- 3b) fp32 -> fp16, both weight matrices in one launch -----
#define WQ4 (3 * C_DIM * C_DIM / 4)
#define WO4 (C_DIM * C_DIM / 4)
__global__ void k_half(const float* __restrict__ wq_src, const float* __restrict__ wo_src,
                       __half* __restrict__ wq_dst, __half* __restrict__ wo_dst) {
    int i = blockIdx.x * blockDim.x + threadIdx.x;
    const float* src; __half* dst; int idx;
    if (i < WQ4) { src = wq_src; dst = wq_dst; idx = i; }
    else if (i < WQ4 + WO4) { src = wo_src; dst = wo_dst; idx = i - WQ4; }
    else return;
    float4 v = __ldcs(&((const float4*)src)[idx]);
    __half hs[4] = { __float2half_rn(v.x), __float2half_rn(v.y),
                     __float2half_rn(v.z), __float2half_rn(v.w) };
    *(uint2*)&dst[idx * 4] = *(uint2*)hs;
}

// ---------------- 4) HMMA GEMM (R4-proven): C = (Ah+Al) B^T + bias ---------
__global__ void __launch_bounds__(256)
k_hgemm(const __half* __restrict__ Ah, const __half* __restrict__ Al,
        const __half* __restrict__ B, const float* __restrict__ bias,
        float* __restrict__ C, int Ncols, int mode, const float* __restrict__ gamma) {
    __shared__ __align__(16) __half sAh[128 * PAD];
    __shared__ __align__(16) __half sAl[128 * PAD];
    __shared__ __align__(16) __half sB [128 * PAD];

    const int tid = threadIdx.x, warp = tid >> 5, lane = tid & 31;
    const int wm = warp >> 2, wn = warp & 3;
    const int bM = blockIdx.y * 128, bN = blockIdx.x * 128;

    float acc[4][4][4];
    #pragma unroll
    for (int i = 0; i < 4; i++)
        #pragma unroll
        for (int j = 0; j < 4; j++)
            #pragma unroll
            for (int c = 0; c < 4; c++) acc[i][j][c] = 0.f;

    const int lr0 = tid >> 2, lc0 = (tid & 3) * 8;
    const int lr1 = (tid + 256) >> 2, lc1 = ((tid + 256) & 3) * 8;

    const int a_row = lane & 15, a_k = (lane >> 4) * 8;
    const int b_row = (lane & 7) + ((lane >> 4) << 3);
    const int b_k   = ((lane >> 3) & 1) * 8;

    const uint32_t sAh_b = smem_u32(sAh), sAl_b = smem_u32(sAl), sB_b = smem_u32(sB);

    for (int k0 = 0; k0 < C_DIM; k0 += 32) {
        __syncthreads();
        {
            size_t ga0 = (size_t)(bM + lr0) * C_DIM + k0 + lc0;
            size_t ga1 = (size_t)(bM + lr1) * C_DIM + k0 + lc1;
            size_t gb0 = (size_t)(bN + lr0) * C_DIM + k0 + lc0;
            size_t gb1 = (size_t)(bN + lr1) * C_DIM + k0 + lc1;
            *(uint4*)&sAh[lr0 * PAD + lc0] = *(const uint4*)&Ah[ga0];
            *(uint4*)&sAh[lr1 * PAD + lc1] = *(const uint4*)&Ah[ga1];
            *(uint4*)&sAl[lr0 * PAD + lc0] = *(const uint4*)&Al[ga0];
            *(uint4*)&sAl[lr1 * PAD + lc1] = *(const uint4*)&Al[ga1];
            *(uint4*)&sB [lr0 * PAD + lc0] = *(const uint4*)&B[gb0];
            *(uint4*)&sB [lr1 * PAD + lc1] = *(const uint4*)&B[gb1];
        }
        __syncthreads();

        #pragma unroll
        for (int ks = 0; ks < 32; ks += 16) {
            uint32_t aH[4][4], aL[4][4], bF[4][2];
            #pragma unroll
            for (int i = 0; i < 4; i++) {
                uint32_t off = (uint32_t)((wm * 64 + i * 16 + a_row) * PAD + ks + a_k) * 2;
                asm volatile("ldmatrix.sync.aligned.m8n8.x4.shared.b16 {%0,%1,%2,%3}, [%4];"
                    : "=r"(aH[i][0]), "=r"(aH[i][1]), "=r"(aH[i][2]), "=r"(aH[i][3])
                    : "r"(sAh_b + off));
                asm volatile("ldmatrix.sync.aligned.m8n8.x4.shared.b16 {%0,%1,%2,%3}, [%4];"
                    : "=r"(aL[i][0]), "=r"(aL[i][1]), "=r"(aL[i][2]), "=r"(aL[i][3])
                    : "r"(sAl_b + off));
            }
            #pragma unroll
            for (int jj = 0; jj < 2; jj++) {
                uint32_t off = (uint32_t)((wn * 32 + jj * 16 + b_row) * PAD + ks + b_k) * 2;
                uint32_t r0, r1, r2, r3;
                asm volatile("ldmatrix.sync.aligned.m8n8.x4.shared.b16 {%0,%1,%2,%3}, [%4];"
                    : "=r"(r0), "=r"(r1), "=r"(r2), "=r"(r3) : "r"(sB_b + off));
                bF[jj * 2 + 0][0] = r0; bF[jj * 2 + 0][1] = r1;
                bF[jj * 2 + 1][0] = r2; bF[jj * 2 + 1][1] = r3;
            }
            #pragma unroll
            for (int i = 0; i < 4; i++)
                #pragma unroll
                for (int j = 0; j < 4; j++) {
                    asm volatile(
                        "mma.sync.aligned.m16n8k16.row.col.f32.f16.f16.f32 "
                        "{%0,%1,%2,%3}, {%4,%5,%6,%7}, {%8,%9}, {%0,%1,%2,%3};"
                        : "+f"(acc[i][j][0]), "+f"(acc[i][j][1]),
                          "+f"(acc[i][j][2]), "+f"(acc[i][j][3])
                        : "r"(aH[i][0]), "r"(aH[i][1]), "r"(aH[i][2]), "r"(aH[i][3]),
                          "r"(bF[j][0]), "r"(bF[j][1]));
                    asm volatile(
                        "mma.sync.aligned.m16n8k16.row.col.f32.f16.f16.f32 "
                        "{%0,%1,%2,%3}, {%4,%5,%6,%7}, {%8,%9}, {%0,%1,%2,%3};"
                        : "+f"(acc[i][j][0]), "+f"(acc[i][j][1]),
                          "+f"(acc[i][j][2]), "+f"(acc[i][j][3])
                        : "r"(aL[i][0]), "r"(aL[i][1]), "r"(aL[i][2]), "r"(aL[i][3]),
                          "r"(bF[j][0]), "r"(bF[j][1]));
                }
        }
    }

    const int g4 = lane >> 2, t4 = lane & 3;
    #pragma unroll
    for (int i = 0; i < 4; i++) {
        int r0 = bM + wm * 64 + i * 16 + g4;
        int r1 = r0 + 8;
        float gm0 = 1.f, gm1 = 1.f;
        if (mode == 1) {
            gm0 = (g_cnt[g_bidx[r0]] > 1) ? gamma[0] : 0.0f;
            gm1 = (g_cnt[g_bidx[r1]] > 1) ? gamma[0] : 0.0f;
        }
        #pragma unroll
        for (int j = 0; j < 4; j++) {
            int c = bN + wn * 32 + j * 8 + 2 * t4;
            float b0 = bias[c], b1 = bias[c + 1];
            float2 o0 = { (acc[i][j][0] + b0) * gm0, (acc[i][j][1] + b1) * gm0 };
            float2 o1 = { (acc[i][j][2] + b0) * gm1, (acc[i][j][3] + b1) * gm1 };
            *(float2*)&C[(size_t)r0 * Ncols + c] = o0;
            *(float2*)&C[(size_t)r1 * Ncols + c] = o1;
        }
    }
}

// ---------------- 5) per-(head,group) flash attention (R4-proven) ----------
#define QCH 32
__global__ void k_attn() {
    int bx = blockIdx.x;
    int qc = bx & (QCH - 1);
    int g  = (bx >> 5) & (NGRP - 1);
    int h  = bx >> 10;
    int m  = g_cnt[g];
    int q0 = qc * 64;
    if (q0 >= m) return;

    int tid = threadIdx.x, w = tid >> 5, lane = tid & 31;
    __shared__ float Ks[32][HD];
    __shared__ float Vs[32][HD];

    float q[8][4], acc[8][4], mx[8], l[8];
    int   tok[8];
    #pragma unroll
    for (int t = 0; t < 8; t++) {
        int qi = q0 + w * 8 + t;
        if (qi < m) {
            tok[t] = g_list[g * N_TOK + qi];
            float4 qv = *(const float4*)&g_qkv[(size_t)tok[t] * 3072 + h * HD + lane * 4];
            q[t][0] = qv.x; q[t][1] = qv.y; q[t][2] = qv.z; q[t][3] = qv.w;
        } else tok[t] = -1;
        mx[t] = -1e30f; l[t] = 0.f;
        acc[t][0] = acc[t][1] = acc[t][2] = acc[t][3] = 0.f;
    }

    int ntile = (m + 31) >> 5;
    for (int kt = 0; kt < ntile; kt++) {
        int kbase = kt * 32;
        #pragma unroll
        for (int it = 0; it < 4; it++) {
            int p  = tid + it * 256;
            int j  = p >> 5, c4 = p & 31;
            int kj = kbase + j;
            float4 kv = {0,0,0,0}, vv = {0,0,0,0};
            if (kj < m) {
                int ktok = g_list[g * N_TOK + kj];
                const float4* b4 = (const float4*)&g_qkv[(size_t)ktok * 3072];
                kv = b4[256 + h * 32 + c4];
                vv = b4[512 + h * 32 + c4];
            }
            *(float4*)&Ks[j][c4 * 4] = kv;
            *(float4*)&Vs[j][c4 * 4] = vv;
        }
        __syncthreads();

        int jmax = m - kbase; if (jmax > 32) jmax = 32;
        for (int j = 0; j < jmax; j++) {
            float4 kj4 = *(const float4*)&Ks[j][lane * 4];
            float4 vj4 = *(const float4*)&Vs[j][lane * 4];
            #pragma unroll
            for (int t = 0; t < 8; t++) {
                if (tok[t] < 0) continue;
                float s = q[t][0] * kj4.x + q[t][1] * kj4.y
                        + q[t][2] * kj4.z + q[t][3] * kj4.w;
                #pragma unroll
                for (int off = 16; off; off >>= 1) s += __shfl_xor_sync(0xffffffffu, s, off);
                s *= 0.08838834764831845f;
                if (s <= mx[t]) {
                    float p = __expf(s - mx[t]);
                    l[t] += p;
                    acc[t][0] += p * vj4.x; acc[t][1] += p * vj4.y;
                    acc[t][2] += p * vj4.z; acc[t][3] += p * vj4.w;
                } else {
                    float corr = __expf(mx[t] - s);
                    l[t] = l[t] * corr + 1.0f;
                    acc[t][0] = acc[t][0] * corr + vj4.x;
                    acc[t][1] = acc[t][1] * corr + vj4.y;
                    acc[t][2] = acc[t][2] * corr + vj4.z;
                    acc[t][3] = acc[t][3] * corr + vj4.w;
                    mx[t] = s;
                }
            }
        }
        __syncthreads();
    }

    #pragma unroll
    for (int t = 0; t < 8; t++) {
        if (tok[t] < 0) continue;
        float inv = 1.0f / l[t];
        float a[4] = { acc[t][0] * inv, acc[t][1] * inv, acc[t][2] * inv, acc[t][3] * inv };
        __half hs[4], ls[4];
        #pragma unroll
        for (int j = 0; j < 4; j++) {
            hs[j] = __float2half_rn(a[j]);
            ls[j] = __float2half_rn(a[j] - __half2float(hs[j]));
        }
        size_t idx = (size_t)tok[t] * C_DIM + h * HD + lane * 4;
        *(uint2*)&g_ah[idx] = *(uint2*)hs;
        *(uint2*)&g_al[idx] = *(uint2*)ls;
    }
}

// ---------------- 6) y = x + coef[n,c] — coalesced, unroll x4 --------------
__global__ void k_add(const float* __restrict__ x, float* __restrict__ y) {
    const float4* x4 = (const float4*)x;
    float4* y4 = (float4*)y;
    const int TOT = N_TOK * C_DIM * 16;           // 2^25 float4
    const int gsize = gridDim.x * blockDim.x;     // 262144 -> 32 exact iters
    int t = blockIdx.x * blockDim.x + threadIdx.x;
    for (int i0 = t; i0 < TOT; i0 += gsize * 4) {
        int  i1 = i0 + gsize, i2 = i0 + 2 * gsize, i3 = i0 + 3 * gsize;
        float4 v0 = __ldcs(&x4[i0]), v1 = __ldcs(&x4[i1]);
        float4 v2 = __ldcs(&x4[i2]), v3 = __ldcs(&x4[i3]);
        float c0 = g_coef[i0 >> 4], c1 = g_coef[i1 >> 4];
        float c2 = g_coef[i2 >> 4], c3 = g_coef[i3 >> 4];
        v0.x += c0; v0.y += c0; v0.z += c0; v0.w += c0;
        v1.x += c1; v1.y += c1; v1.z += c1; v1.w += c1;
        v2.x += c2; v2.y += c2; v2.z += c2; v2.w += c2;
        v3.x += c3; v3.y += c3; v3.z += c3; v3.w += c3;
        __stcs(&y4[i0], v0); __stcs(&y4[i1], v1);
        __stcs(&y4[i2], v2); __stcs(&y4[i3], v3);
    }
}

// ---------------- launch ---------------------------------------------------
extern "C" void kernel_launch(void* const* d_in, const int* in_sizes, int n_in,
                              void* d_out, int out_size) {
    const float* x          = (const float*)d_in[0];
    const int*   braw       = (const int*)  d_in[1];
    const float* ln_w       = (const float*)d_in[2];
    const float* ln_b       = (const float*)d_in[3];
    const float* in_proj_w  = (const float*)d_in[4];
    const float* in_proj_b  = (const float*)d_in[5];
    const float* out_proj_w = (const float*)d_in[6];
    const float* out_proj_b = (const float*)d_in[7];
    const float* gamma      = (const float*)d_in[8];
    float* y = (float*)d_out;

    __half *p_fh, *p_fl, *p_wq, *p_wo, *p_ah, *p_al;
    float *p_qkv, *p_coef;
    cudaGetSymbolAddress((void**)&p_fh,  g_fh);
    cudaGetSymbolAddress((void**)&p_fl,  g_fl);
    cudaGetSymbolAddress((void**)&p_wq,  g_wq);
    cudaGetSymbolAddress((void**)&p_wo,  g_wo);
    cudaGetSymbolAddress((void**)&p_ah,  g_ah);
    cudaGetSymbolAddress((void**)&p_al,  g_al);
    cudaGetSymbolAddress((void**)&p_qkv, g_qkv);
    cudaGetSymbolAddress((void**)&p_coef, g_coef);

    k_groups <<<8, 256>>>(braw);
    k_mean   <<<1184, 256>>>(x);
    k_ln     <<<N_TOK, 256>>>(ln_w, ln_b);
    k_half   <<<4096, 256>>>(in_proj_w, out_proj_w, p_wq, p_wo);
    k_hgemm  <<<dim3(24, 16), 256>>>(p_fh, p_fl, p_wq, in_proj_b, p_qkv,
                                     3 * C_DIM, 0, nullptr);
    k_attn   <<<NHEAD * NGRP * QCH, 256>>>();
    k_hgemm  <<<dim3(8, 16), 256>>>(p_ah, p_al, p_wo, out_proj_b, p_coef,
                                    C_DIM, 1, gamma);
    k_add    <<<1024, 256>>>(x, y);
}

// round 7
// speedup vs baseline: 1.2547x; 1.0327x over previous
#include <cuda_runtime.h>
#include <cuda_fp16.h>
#include <stdint.h>
#include <math.h>

#define N_TOK 2048
#define C_DIM 1024
#define NHEAD 8
#define HD    128
#define NGRP  32
#define HW    64
#define PAD   40   // smem row stride in halfs (80B, multiple of 16B, conflict-free)

// ---------------- scratch (device globals: allocation-free) ----------------
__device__ float g_feat[N_TOK * C_DIM];
__device__ float g_qkv [N_TOK * 3 * C_DIM];
__device__ float g_coef[N_TOK * C_DIM];
__device__ int   g_bidx[N_TOK];
__device__ int   g_cnt [NGRP];
__device__ int   g_list[NGRP * N_TOK];
__device__ __half g_fh [N_TOK * C_DIM], g_fl [N_TOK * C_DIM];
__device__ __half g_wq [3 * C_DIM * C_DIM];
__device__ __half g_wo [C_DIM * C_DIM];
__device__ __half g_ah [N_TOK * C_DIM], g_al [N_TOK * C_DIM];

__device__ __forceinline__ uint32_t smem_u32(const void* p) {
    uint32_t a;
    asm("{ .reg .u64 t; cvta.to.shared.u64 t, %1; cvt.u32.u64 %0, t; }" : "=r"(a) : "l"(p));
    return a;
}

// ---------------- 1) groups: detect width, lists + counts ------------------
__global__ void k_groups(const int* __restrict__ raw) {
    __shared__ int sb[N_TOK];
    __shared__ int s64;
    if (threadIdx.x == 0) {
        int acc = 0;
        #pragma unroll
        for (int i = 0; i < 32; i++) acc |= raw[2 * i + 1];
        s64 = (acc == 0);
    }
    __syncthreads();
    for (int i = threadIdx.x; i < N_TOK; i += blockDim.x)
        sb[i] = s64 ? raw[2 * i] : raw[i];
    __syncthreads();
    int i = blockIdx.x * blockDim.x + threadIdx.x;   // grid 8 x 256
    if (blockIdx.x == 0) {
        for (int j = threadIdx.x; j < N_TOK; j += blockDim.x) g_bidx[j] = sb[j];
    }
    int b = sb[i];
    int pos = 0;
    for (int j = 0; j < i; j++) pos += (sb[j] == b) ? 1 : 0;
    g_list[b * N_TOK + pos] = i;
    if (blockIdx.x == 0 && threadIdx.x < NGRP) {
        int c = 0;
        for (int j = 0; j < N_TOK; j++) c += (sb[j] == (int)threadIdx.x) ? 1 : 0;
        g_cnt[threadIdx.x] = c;
    }
}

// ---------------- 2) feat = mean over H*W -----------------------------------
// Warp handles a 4KB chunk (16 rows) via 8 independent, lane-coalesced LDG.128.
__global__ void k_mean(const float* __restrict__ x) {
    const float4* x4 = (const float4*)x;
    int gw    = (blockIdx.x * blockDim.x + threadIdx.x) >> 5;
    int lane  = threadIdx.x & 31;
    int nwarp = (gridDim.x * blockDim.x) >> 5;
    const int CHUNKS = N_TOK * C_DIM / 16;        // 131072 chunks of 16 rows
    for (int ch = gw; ch < CHUNKS; ch += nwarp) {
        size_t base = (size_t)ch * 256 + lane;
        float4 v[8];
        #pragma unroll
        for (int j = 0; j < 8; j++) v[j] = __ldcs(&x4[base + 32 * j]);
        float s[8];
        #pragma unroll
        for (int j = 0; j < 8; j++) s[j] = (v[j].x + v[j].y) + (v[j].z + v[j].w);
        #pragma unroll
        for (int j = 0; j < 8; j++) {
            s[j] += __shfl_xor_sync(0xffffffffu, s[j], 8);
            s[j] += __shfl_xor_sync(0xffffffffu, s[j], 4);
            s[j] += __shfl_xor_sync(0xffffffffu, s[j], 2);
            s[j] += __shfl_xor_sync(0xffffffffu, s[j], 1);
        }
        if (lane == 0 || lane == 16) {
            int r0 = ch * 16 + (lane >> 4);
            #pragma unroll
            for (int j = 0; j < 8; j++) g_feat[r0 + 2 * j] = s[j] * (1.0f / 64.0f);
        }
    }
}

// ---------------- 3) LayerNorm over C, emit fp16 hi/lo ---------------------
__global__ void k_ln(const float* __restrict__ w, const float* __restrict__ b) {
    int row = blockIdx.x, tid = threadIdx.x;
    int lane = tid & 31, warp = tid >> 5;
    float4 v = ((const float4*)g_feat)[row * 256 + tid];
    float s  = v.x + v.y + v.z + v.w;
    float sq = v.x * v.x + v.y * v.y + v.z * v.z + v.w * v.w;
    #pragma unroll
    for (int off = 16; off; off >>= 1) {
        s  += __shfl_xor_sync(0xffffffffu, s,  off);
        sq += __shfl_xor_sync(0xffffffffu, sq, off);
    }
    __shared__ float rs[8], rq[8];
    if (lane == 0) { rs[warp] = s; rq[warp] = sq; }
    __syncthreads();
    float S = 0.f, SQ = 0.f;
    #pragma unroll
    for (int i = 0; i < 8; i++) { S += rs[i]; SQ += rq[i]; }
    float mu   = S * (1.0f / C_DIM);
    float var  = SQ * (1.0f / C_DIM) - mu * mu;
    float rstd = rsqrtf(var + 1e-5f);
    float4 wv = ((const float4*)w)[tid], bv = ((const float4*)b)[tid];
    float a[4];
    a[0] = (v.x - mu) * rstd * wv.x + bv.x;
    a[1] = (v.y - mu) * rstd * wv.y + bv.y;
    a[2] = (v.z - mu) * rstd * wv.z + bv.z;
    a[3] = (v.w - mu) * rstd * wv.w + bv.w;
    __half hs[4], ls[4];
    #pragma unroll
    for (int j = 0; j < 4; j++) {
        hs[j] = __float2half_rn(a[j]);
        ls[j] = __float2half_rn(a[j] - __half2float(hs[j]));
    }
    *(uint2*)&g_fh[row * C_DIM + tid * 4] = *(uint2*)hs;
    *(uint2*)&g_fl[row * C_DIM + tid * 4] = *(uint2*)ls;
}

// ---------------- 3b) fp32 -> fp16 (weights) -------------------------------
__global__ void k_half(const float* __restrict__ src, __half* __restrict__ dst, int n4) {
    int i = blockIdx.x * blockDim.x + threadIdx.x;
    if (i >= n4) return;
    float4 v = __ldcs(&((const float4*)src)[i]);
    __half hs[4] = { __float2half_rn(v.x), __float2half_rn(v.y),
                     __float2half_rn(v.z), __float2half_rn(v.w) };
    *(uint2*)&dst[i * 4] = *(uint2*)hs;
}

// ---------------- 4) HMMA GEMM (R4-proven): C = (Ah+Al) B^T + bias ---------
__global__ void __launch_bounds__(256)
k_hgemm(const __half* __restrict__ Ah, const __half* __restrict__ Al,
        const __half* __restrict__ B, const float* __restrict__ bias,
        float* __restrict__ C, int Ncols, int mode, const float* __restrict__ gamma) {
    __shared__ __align__(16) __half sAh[128 * PAD];
    __shared__ __align__(16) __half sAl[128 * PAD];
    __shared__ __align__(16) __half sB [128 * PAD];

    const int tid = threadIdx.x, warp = tid >> 5, lane = tid & 31;
    const int wm = warp >> 2, wn = warp & 3;
    const int bM = blockIdx.y * 128, bN = blockIdx.x * 128;

    float acc[4][4][4];
    #pragma unroll
    for (int i = 0; i < 4; i++)
        #pragma unroll
        for (int j = 0; j < 4; j++)
            #pragma unroll
            for (int c = 0; c < 4; c++) acc[i][j][c] = 0.f;

    const int lr0 = tid >> 2, lc0 = (tid & 3) * 8;
    const int lr1 = (tid + 256) >> 2, lc1 = ((tid + 256) & 3) * 8;

    const int a_row = lane & 15, a_k = (lane >> 4) * 8;
    const int b_row = (lane & 7) + ((lane >> 4) << 3);
    const int b_k   = ((lane >> 3) & 1) * 8;

    const uint32_t sAh_b = smem_u32(sAh), sAl_b = smem_u32(sAl), sB_b = smem_u32(sB);

    for (int k0 = 0; k0 < C_DIM; k0 += 32) {
        __syncthreads();
        {
            size_t ga0 = (size_t)(bM + lr0) * C_DIM + k0 + lc0;
            size_t ga1 = (size_t)(bM + lr1) * C_DIM + k0 + lc1;
            size_t gb0 = (size_t)(bN + lr0) * C_DIM + k0 + lc0;
            size_t gb1 = (size_t)(bN + lr1) * C_DIM + k0 + lc1;
            *(uint4*)&sAh[lr0 * PAD + lc0] = *(const uint4*)&Ah[ga0];
            *(uint4*)&sAh[lr1 * PAD + lc1] = *(const uint4*)&Ah[ga1];
            *(uint4*)&sAl[lr0 * PAD + lc0] = *(const uint4*)&Al[ga0];
            *(uint4*)&sAl[lr1 * PAD + lc1] = *(const uint4*)&Al[ga1];
            *(uint4*)&sB [lr0 * PAD + lc0] = *(const uint4*)&B[gb0];
            *(uint4*)&sB [lr1 * PAD + lc1] = *(const uint4*)&B[gb1];
        }
        __syncthreads();

        #pragma unroll
        for (int ks = 0; ks < 32; ks += 16) {
            uint32_t aH[4][4], aL[4][4], bF[4][2];
            #pragma unroll
            for (int i = 0; i < 4; i++) {
                uint32_t off = (uint32_t)((wm * 64 + i * 16 + a_row) * PAD + ks + a_k) * 2;
                asm volatile("ldmatrix.sync.aligned.m8n8.x4.shared.b16 {%0,%1,%2,%3}, [%4];"
                    : "=r"(aH[i][0]), "=r"(aH[i][1]), "=r"(aH[i][2]), "=r"(aH[i][3])
                    : "r"(sAh_b + off));
                asm volatile("ldmatrix.sync.aligned.m8n8.x4.shared.b16 {%0,%1,%2,%3}, [%4];"
                    : "=r"(aL[i][0]), "=r"(aL[i][1]), "=r"(aL[i][2]), "=r"(aL[i][3])
                    : "r"(sAl_b + off));
            }
            #pragma unroll
            for (int jj = 0; jj < 2; jj++) {
                uint32_t off = (uint32_t)((wn * 32 + jj * 16 + b_row) * PAD + ks + b_k) * 2;
                uint32_t r0, r1, r2, r3;
                asm volatile("ldmatrix.sync.aligned.m8n8.x4.shared.b16 {%0,%1,%2,%3}, [%4];"
                    : "=r"(r0), "=r"(r1), "=r"(r2), "=r"(r3) : "r"(sB_b + off));
                bF[jj * 2 + 0][0] = r0; bF[jj * 2 + 0][1] = r1;
                bF[jj * 2 + 1][0] = r2; bF[jj * 2 + 1][1] = r3;
            }
            #pragma unroll
            for (int i = 0; i < 4; i++)
                #pragma unroll
                for (int j = 0; j < 4; j++) {
                    asm volatile(
                        "mma.sync.aligned.m16n8k16.row.col.f32.f16.f16.f32 "
                        "{%0,%1,%2,%3}, {%4,%5,%6,%7}, {%8,%9}, {%0,%1,%2,%3};"
                        : "+f"(acc[i][j][0]), "+f"(acc[i][j][1]),
                          "+f"(acc[i][j][2]), "+f"(acc[i][j][3])
                        : "r"(aH[i][0]), "r"(aH[i][1]), "r"(aH[i][2]), "r"(aH[i][3]),
                          "r"(bF[j][0]), "r"(bF[j][1]));
                    asm volatile(
                        "mma.sync.aligned.m16n8k16.row.col.f32.f16.f16.f32 "
                        "{%0,%1,%2,%3}, {%4,%5,%6,%7}, {%8,%9}, {%0,%1,%2,%3};"
                        : "+f"(acc[i][j][0]), "+f"(acc[i][j][1]),
                          "+f"(acc[i][j][2]), "+f"(acc[i][j][3])
                        : "r"(aL[i][0]), "r"(aL[i][1]), "r"(aL[i][2]), "r"(aL[i][3]),
                          "r"(bF[j][0]), "r"(bF[j][1]));
                }
        }
    }

    const int g4 = lane >> 2, t4 = lane & 3;
    #pragma unroll
    for (int i = 0; i < 4; i++) {
        int r0 = bM + wm * 64 + i * 16 + g4;
        int r1 = r0 + 8;
        float gm0 = 1.f, gm1 = 1.f;
        if (mode == 1) {
            gm0 = (g_cnt[g_bidx[r0]] > 1) ? gamma[0] : 0.0f;
            gm1 = (g_cnt[g_bidx[r1]] > 1) ? gamma[0] : 0.0f;
        }
        #pragma unroll
        for (int j = 0; j < 4; j++) {
            int c = bN + wn * 32 + j * 8 + 2 * t4;
            float b0 = bias[c], b1 = bias[c + 1];
            float2 o0 = { (acc[i][j][0] + b0) * gm0, (acc[i][j][1] + b1) * gm0 };
            float2 o1 = { (acc[i][j][2] + b0) * gm1, (acc[i][j][3] + b1) * gm1 };
            *(float2*)&C[(size_t)r0 * Ncols + c] = o0;
            *(float2*)&C[(size_t)r1 * Ncols + c] = o1;
        }
    }
}

// ---------------- 5) per-(head,group) flash attention (R4-proven) ----------
#define QCH 32
__global__ void k_attn() {
    int bx = blockIdx.x;
    int qc = bx & (QCH - 1);
    int g  = (bx >> 5) & (NGRP - 1);
    int h  = bx >> 10;
    int m  = g_cnt[g];
    int q0 = qc * 64;
    if (q0 >= m) return;

    int tid = threadIdx.x, w = tid >> 5, lane = tid & 31;
    __shared__ float Ks[32][HD];
    __shared__ float Vs[32][HD];

    float q[8][4], acc[8][4], mx[8], l[8];
    int   tok[8];
    #pragma unroll
    for (int t = 0; t < 8; t++) {
        int qi = q0 + w * 8 + t;
        if (qi < m) {
            tok[t] = g_list[g * N_TOK + qi];
            float4 qv = *(const float4*)&g_qkv[(size_t)tok[t] * 3072 + h * HD + lane * 4];
            q[t][0] = qv.x; q[t][1] = qv.y; q[t][2] = qv.z; q[t][3] = qv.w;
        } else tok[t] = -1;
        mx[t] = -1e30f; l[t] = 0.f;
        acc[t][0] = acc[t][1] = acc[t][2] = acc[t][3] = 0.f;
    }

    int ntile = (m + 31) >> 5;
    for (int kt = 0; kt < ntile; kt++) {
        int kbase = kt * 32;
        #pragma unroll
        for (int it = 0; it < 4; it++) {
            int p  = tid + it * 256;
            int j  = p >> 5, c4 = p & 31;
            int kj = kbase + j;
            float4 kv = {0,0,0,0}, vv = {0,0,0,0};
            if (kj < m) {
                int ktok = g_list[g * N_TOK + kj];
                const float4* b4 = (const float4*)&g_qkv[(size_t)ktok * 3072];
                kv = b4[256 + h * 32 + c4];
                vv = b4[512 + h * 32 + c4];
            }
            *(float4*)&Ks[j][c4 * 4] = kv;
            *(float4*)&Vs[j][c4 * 4] = vv;
        }
        __syncthreads();

        int jmax = m - kbase; if (jmax > 32) jmax = 32;
        for (int j = 0; j < jmax; j++) {
            float4 kj4 = *(const float4*)&Ks[j][lane * 4];
            float4 vj4 = *(const float4*)&Vs[j][lane * 4];
            #pragma unroll
            for (int t = 0; t < 8; t++) {
                if (tok[t] < 0) continue;
                float s = q[t][0] * kj4.x + q[t][1] * kj4.y
                        + q[t][2] * kj4.z + q[t][3] * kj4.w;
                #pragma unroll
                for (int off = 16; off; off >>= 1) s += __shfl_xor_sync(0xffffffffu, s, off);
                s *= 0.08838834764831845f;
                if (s <= mx[t]) {
                    float p = __expf(s - mx[t]);
                    l[t] += p;
                    acc[t][0] += p * vj4.x; acc[t][1] += p * vj4.y;
                    acc[t][2] += p * vj4.z; acc[t][3] += p * vj4.w;
                } else {
                    float corr = __expf(mx[t] - s);
                    l[t] = l[t] * corr + 1.0f;
                    acc[t][0] = acc[t][0] * corr + vj4.x;
                    acc[t][1] = acc[t][1] * corr + vj4.y;
                    acc[t][2] = acc[t][2] * corr + vj4.z;
                    acc[t][3] = acc[t][3] * corr + vj4.w;
                    mx[t] = s;
                }
            }
        }
        __syncthreads();
    }

    #pragma unroll
    for (int t = 0; t < 8; t++) {
        if (tok[t] < 0) continue;
        float inv = 1.0f / l[t];
        float a[4] = { acc[t][0] * inv, acc[t][1] * inv, acc[t][2] * inv, acc[t][3] * inv };
        __half hs[4], ls[4];
        #pragma unroll
        for (int j = 0; j < 4; j++) {
            hs[j] = __float2half_rn(a[j]);
            ls[j] = __float2half_rn(a[j] - __half2float(hs[j]));
        }
        size_t idx = (size_t)tok[t] * C_DIM + h * HD + lane * 4;
        *(uint2*)&g_ah[idx] = *(uint2*)hs;
        *(uint2*)&g_al[idx] = *(uint2*)ls;
    }
}

// ---------------- 6) y = x + coef[n,c] (R4-proven simple version) ----------
__global__ void k_add(const float* __restrict__ x, float* __restrict__ y) {
    const float4* x4 = (const float4*)x;
    float4* y4 = (float4*)y;
    const int total = N_TOK * C_DIM * (HW / 4);   // 2^25 float4
    int stride = gridDim.x * blockDim.x;
    for (int i = blockIdx.x * blockDim.x + threadIdx.x; i < total; i += stride) {
        float c = g_coef[i >> 4];
        float4 v = x4[i];
        v.x += c; v.y += c; v.z += c; v.w += c;
        y4[i] = v;
    }
}

// ---------------- launch ---------------------------------------------------
extern "C" void kernel_launch(void* const* d_in, const int* in_sizes, int n_in,
                              void* d_out, int out_size) {
    const float* x          = (const float*)d_in[0];
    const int*   braw       = (const int*)  d_in[1];
    const float* ln_w       = (const float*)d_in[2];
    const float* ln_b       = (const float*)d_in[3];
    const float* in_proj_w  = (const float*)d_in[4];
    const float* in_proj_b  = (const float*)d_in[5];
    const float* out_proj_w = (const float*)d_in[6];
    const float* out_proj_b = (const float*)d_in[7];
    const float* gamma      = (const float*)d_in[8];
    float* y = (float*)d_out;

    __half *p_fh, *p_fl, *p_wq, *p_wo, *p_ah, *p_al;
    float *p_qkv, *p_coef;
    cudaGetSymbolAddress((void**)&p_fh,  g_fh);
    cudaGetSymbolAddress((void**)&p_fl,  g_fl);
    cudaGetSymbolAddress((void**)&p_wq,  g_wq);
    cudaGetSymbolAddress((void**)&p_wo,  g_wo);
    cudaGetSymbolAddress((void**)&p_ah,  g_ah);
    cudaGetSymbolAddress((void**)&p_al,  g_al);
    cudaGetSymbolAddress((void**)&p_qkv, g_qkv);
    cudaGetSymbolAddress((void**)&p_coef, g_coef);

    // Launch order arranged so k_mean sits in profiling slot #4.
    k_half   <<<3072, 256>>>(in_proj_w,  p_wq, 3 * C_DIM * C_DIM / 4);
    k_half   <<<1024, 256>>>(out_proj_w, p_wo, C_DIM * C_DIM / 4);
    k_groups <<<8, 256>>>(braw);
    k_mean   <<<1184, 256>>>(x);
    k_ln     <<<N_TOK, 256>>>(ln_w, ln_b);
    k_hgemm  <<<dim3(24, 16), 256>>>(p_fh, p_fl, p_wq, in_proj_b, p_qkv,
                                     3 * C_DIM, 0, nullptr);
    k_attn   <<<NHEAD * NGRP * QCH, 256>>>();
    k_hgemm  <<<dim3(8, 16), 256>>>(p_ah, p_al, p_wo, out_proj_b, p_coef,
                                    C_DIM, 1, gamma);
    k_add    <<<32768, 256>>>(x, y);
}

// round 8
// speedup vs baseline: 1.2563x; 1.0013x over previous
#include <cuda_runtime.h>
#include <cuda_fp16.h>
#include <stdint.h>
#include <math.h>

#define N_TOK 2048
#define C_DIM 1024
#define NHEAD 8
#define HD    128
#define NGRP  32
#define HW    64
#define PAD   40   // smem row stride in halfs (80B, multiple of 16B, conflict-free)

// ---------------- scratch (device globals: allocation-free) ----------------
__device__ float g_feat[N_TOK * C_DIM];
__device__ float g_qkv [N_TOK * 3 * C_DIM];
__device__ float g_coef[N_TOK * C_DIM];
__device__ int   g_bidx[N_TOK];
__device__ int   g_cnt [NGRP];
__device__ int   g_list[NGRP * N_TOK];
__device__ __half g_fh [N_TOK * C_DIM], g_fl [N_TOK * C_DIM];
__device__ __half g_wq [3 * C_DIM * C_DIM];
__device__ __half g_wo [C_DIM * C_DIM];
__device__ __half g_ah [N_TOK * C_DIM], g_al [N_TOK * C_DIM];

__device__ __forceinline__ uint32_t smem_u32(const void* p) {
    uint32_t a;
    asm("{ .reg .u64 t; cvta.to.shared.u64 t, %1; cvt.u32.u64 %0, t; }" : "=r"(a) : "l"(p));
    return a;
}

// ---------------- 1) groups: detect width, lists + counts ------------------
__global__ void k_groups(const int* __restrict__ raw) {
    __shared__ int sb[N_TOK];
    __shared__ int s64;
    if (threadIdx.x == 0) {
        int acc = 0;
        #pragma unroll
        for (int i = 0; i < 32; i++) acc |= raw[2 * i + 1];
        s64 = (acc == 0);
    }
    __syncthreads();
    for (int i = threadIdx.x; i < N_TOK; i += blockDim.x)
        sb[i] = s64 ? raw[2 * i] : raw[i];
    __syncthreads();
    int i = blockIdx.x * blockDim.x + threadIdx.x;   // grid 8 x 256
    if (blockIdx.x == 0) {
        for (int j = threadIdx.x; j < N_TOK; j += blockDim.x) g_bidx[j] = sb[j];
    }
    int b = sb[i];
    int pos = 0;
    for (int j = 0; j < i; j++) pos += (sb[j] == b) ? 1 : 0;
    g_list[b * N_TOK + pos] = i;
    if (blockIdx.x == 0 && threadIdx.x < NGRP) {
        int c = 0;
        for (int j = 0; j < N_TOK; j++) c += (sb[j] == (int)threadIdx.x) ? 1 : 0;
        g_cnt[threadIdx.x] = c;
    }
}

// ---------------- 2) feat = mean over H*W -----------------------------------
// Warp handles a 4KB chunk (16 rows) via 8 independent, lane-coalesced LDG.128.
__global__ void k_mean(const float* __restrict__ x) {
    const float4* x4 = (const float4*)x;
    int gw    = (blockIdx.x * blockDim.x + threadIdx.x) >> 5;
    int lane  = threadIdx.x & 31;
    int nwarp = (gridDim.x * blockDim.x) >> 5;
    const int CHUNKS = N_TOK * C_DIM / 16;        // 131072 chunks of 16 rows
    for (int ch = gw; ch < CHUNKS; ch += nwarp) {
        size_t base = (size_t)ch * 256 + lane;
        float4 v[8];
        #pragma unroll
        for (int j = 0; j < 8; j++) v[j] = __ldcs(&x4[base + 32 * j]);
        float s[8];
        #pragma unroll
        for (int j = 0; j < 8; j++) s[j] = (v[j].x + v[j].y) + (v[j].z + v[j].w);
        #pragma unroll
        for (int j = 0; j < 8; j++) {
            s[j] += __shfl_xor_sync(0xffffffffu, s[j], 8);
            s[j] += __shfl_xor_sync(0xffffffffu, s[j], 4);
            s[j] += __shfl_xor_sync(0xffffffffu, s[j], 2);
            s[j] += __shfl_xor_sync(0xffffffffu, s[j], 1);
        }
        if (lane == 0 || lane == 16) {
            int r0 = ch * 16 + (lane >> 4);
            #pragma unroll
            for (int j = 0; j < 8; j++) g_feat[r0 + 2 * j] = s[j] * (1.0f / 64.0f);
        }
    }
}

// ---------------- 3) LayerNorm over C, emit fp16 hi/lo ---------------------
__global__ void k_ln(const float* __restrict__ w, const float* __restrict__ b) {
    int row = blockIdx.x, tid = threadIdx.x;
    int lane = tid & 31, warp = tid >> 5;
    float4 v = ((const float4*)g_feat)[row * 256 + tid];
    float s  = v.x + v.y + v.z + v.w;
    float sq = v.x * v.x + v.y * v.y + v.z * v.z + v.w * v.w;
    #pragma unroll
    for (int off = 16; off; off >>= 1) {
        s  += __shfl_xor_sync(0xffffffffu, s,  off);
        sq += __shfl_xor_sync(0xffffffffu, sq, off);
    }
    __shared__ float rs[8], rq[8];
    if (lane == 0) { rs[warp] = s; rq[warp] = sq; }
    __syncthreads();
    float S = 0.f, SQ = 0.f;
    #pragma unroll
    for (int i = 0; i < 8; i++) { S += rs[i]; SQ += rq[i]; }
    float mu   = S * (1.0f / C_DIM);
    float var  = SQ * (1.0f / C_DIM) - mu * mu;
    float rstd = rsqrtf(var + 1e-5f);
    float4 wv = ((const float4*)w)[tid], bv = ((const float4*)b)[tid];
    float a[4];
    a[0] = (v.x - mu) * rstd * wv.x + bv.x;
    a[1] = (v.y - mu) * rstd * wv.y + bv.y;
    a[2] = (v.z - mu) * rstd * wv.z + bv.z;
    a[3] = (v.w - mu) * rstd * wv.w + bv.w;
    __half hs[4], ls[4];
    #pragma unroll
    for (int j = 0; j < 4; j++) {
        hs[j] = __float2half_rn(a[j]);
        ls[j] = __float2half_rn(a[j] - __half2float(hs[j]));
    }
    *(uint2*)&g_fh[row * C_DIM + tid * 4] = *(uint2*)hs;
    *(uint2*)&g_fl[row * C_DIM + tid * 4] = *(uint2*)ls;
}

// ---------------- 3b) fp32 -> fp16 (weights) -------------------------------
__global__ void k_half(const float* __restrict__ src, __half* __restrict__ dst, int n4) {
    int i = blockIdx.x * blockDim.x + threadIdx.x;
    if (i >= n4) return;
    float4 v = __ldcs(&((const float4*)src)[i]);
    __half hs[4] = { __float2half_rn(v.x), __float2half_rn(v.y),
                     __float2half_rn(v.z), __float2half_rn(v.w) };
    *(uint2*)&dst[i * 4] = *(uint2*)hs;
}

// ---------------- 4) HMMA GEMM (R4-proven): C = (Ah+Al) B^T + bias ---------
__global__ void __launch_bounds__(256)
k_hgemm(const __half* __restrict__ Ah, const __half* __restrict__ Al,
        const __half* __restrict__ B, const float* __restrict__ bias,
        float* __restrict__ C, int Ncols, int mode, const float* __restrict__ gamma) {
    __shared__ __align__(16) __half sAh[128 * PAD];
    __shared__ __align__(16) __half sAl[128 * PAD];
    __shared__ __align__(16) __half sB [128 * PAD];

    const int tid = threadIdx.x, warp = tid >> 5, lane = tid & 31;
    const int wm = warp >> 2, wn = warp & 3;
    const int bM = blockIdx.y * 128, bN = blockIdx.x * 128;

    float acc[4][4][4];
    #pragma unroll
    for (int i = 0; i < 4; i++)
        #pragma unroll
        for (int j = 0; j < 4; j++)
            #pragma unroll
            for (int c = 0; c < 4; c++) acc[i][j][c] = 0.f;

    const int lr0 = tid >> 2, lc0 = (tid & 3) * 8;
    const int lr1 = (tid + 256) >> 2, lc1 = ((tid + 256) & 3) * 8;

    const int a_row = lane & 15, a_k = (lane >> 4) * 8;
    const int b_row = (lane & 7) + ((lane >> 4) << 3);
    const int b_k   = ((lane >> 3) & 1) * 8;

    const uint32_t sAh_b = smem_u32(sAh), sAl_b = smem_u32(sAl), sB_b = smem_u32(sB);

    for (int k0 = 0; k0 < C_DIM; k0 += 32) {
        __syncthreads();
        {
            size_t ga0 = (size_t)(bM + lr0) * C_DIM + k0 + lc0;
            size_t ga1 = (size_t)(bM + lr1) * C_DIM + k0 + lc1;
            size_t gb0 = (size_t)(bN + lr0) * C_DIM + k0 + lc0;
            size_t gb1 = (size_t)(bN + lr1) * C_DIM + k0 + lc1;
            *(uint4*)&sAh[lr0 * PAD + lc0] = *(const uint4*)&Ah[ga0];
            *(uint4*)&sAh[lr1 * PAD + lc1] = *(const uint4*)&Ah[ga1];
            *(uint4*)&sAl[lr0 * PAD + lc0] = *(const uint4*)&Al[ga0];
            *(uint4*)&sAl[lr1 * PAD + lc1] = *(const uint4*)&Al[ga1];
            *(uint4*)&sB [lr0 * PAD + lc0] = *(const uint4*)&B[gb0];
            *(uint4*)&sB [lr1 * PAD + lc1] = *(const uint4*)&B[gb1];
        }
        __syncthreads();

        #pragma unroll
        for (int ks = 0; ks < 32; ks += 16) {
            uint32_t aH[4][4], aL[4][4], bF[4][2];
            #pragma unroll
            for (int i = 0; i < 4; i++) {
                uint32_t off = (uint32_t)((wm * 64 + i * 16 + a_row) * PAD + ks + a_k) * 2;
                asm volatile("ldmatrix.sync.aligned.m8n8.x4.shared.b16 {%0,%1,%2,%3}, [%4];"
                    : "=r"(aH[i][0]), "=r"(aH[i][1]), "=r"(aH[i][2]), "=r"(aH[i][3])
                    : "r"(sAh_b + off));
                asm volatile("ldmatrix.sync.aligned.m8n8.x4.shared.b16 {%0,%1,%2,%3}, [%4];"
                    : "=r"(aL[i][0]), "=r"(aL[i][1]), "=r"(aL[i][2]), "=r"(aL[i][3])
                    : "r"(sAl_b + off));
            }
            #pragma unroll
            for (int jj = 0; jj < 2; jj++) {
                uint32_t off = (uint32_t)((wn * 32 + jj * 16 + b_row) * PAD + ks + b_k) * 2;
                uint32_t r0, r1, r2, r3;
                asm volatile("ldmatrix.sync.aligned.m8n8.x4.shared.b16 {%0,%1,%2,%3}, [%4];"
                    : "=r"(r0), "=r"(r1), "=r"(r2), "=r"(r3) : "r"(sB_b + off));
                bF[jj * 2 + 0][0] = r0; bF[jj * 2 + 0][1] = r1;
                bF[jj * 2 + 1][0] = r2; bF[jj * 2 + 1][1] = r3;
            }
            #pragma unroll
            for (int i = 0; i < 4; i++)
                #pragma unroll
                for (int j = 0; j < 4; j++) {
                    asm volatile(
                        "mma.sync.aligned.m16n8k16.row.col.f32.f16.f16.f32 "
                        "{%0,%1,%2,%3}, {%4,%5,%6,%7}, {%8,%9}, {%0,%1,%2,%3};"
                        : "+f"(acc[i][j][0]), "+f"(acc[i][j][1]),
                          "+f"(acc[i][j][2]), "+f"(acc[i][j][3])
                        : "r"(aH[i][0]), "r"(aH[i][1]), "r"(aH[i][2]), "r"(aH[i][3]),
                          "r"(bF[j][0]), "r"(bF[j][1]));
                    asm volatile(
                        "mma.sync.aligned.m16n8k16.row.col.f32.f16.f16.f32 "
                        "{%0,%1,%2,%3}, {%4,%5,%6,%7}, {%8,%9}, {%0,%1,%2,%3};"
                        : "+f"(acc[i][j][0]), "+f"(acc[i][j][1]),
                          "+f"(acc[i][j][2]), "+f"(acc[i][j][3])
                        : "r"(aL[i][0]), "r"(aL[i][1]), "r"(aL[i][2]), "r"(aL[i][3]),
                          "r"(bF[j][0]), "r"(bF[j][1]));
                }
        }
    }

    const int g4 = lane >> 2, t4 = lane & 3;
    #pragma unroll
    for (int i = 0; i < 4; i++) {
        int r0 = bM + wm * 64 + i * 16 + g4;
        int r1 = r0 + 8;
        float gm0 = 1.f, gm1 = 1.f;
        if (mode == 1) {
            gm0 = (g_cnt[g_bidx[r0]] > 1) ? gamma[0] : 0.0f;
            gm1 = (g_cnt[g_bidx[r1]] > 1) ? gamma[0] : 0.0f;
        }
        #pragma unroll
        for (int j = 0; j < 4; j++) {
            int c = bN + wn * 32 + j * 8 + 2 * t4;
            float b0 = bias[c], b1 = bias[c + 1];
            float2 o0 = { (acc[i][j][0] + b0) * gm0, (acc[i][j][1] + b1) * gm0 };
            float2 o1 = { (acc[i][j][2] + b0) * gm1, (acc[i][j][3] + b1) * gm1 };
            *(float2*)&C[(size_t)r0 * Ncols + c] = o0;
            *(float2*)&C[(size_t)r1 * Ncols + c] = o1;
        }
    }
}

// ---------------- 5) per-(head,group) flash attention (R4-proven) ----------
#define QCH 32
__global__ void k_attn() {
    int bx = blockIdx.x;
    int qc = bx & (QCH - 1);
    int g  = (bx >> 5) & (NGRP - 1);
    int h  = bx >> 10;
    int m  = g_cnt[g];
    int q0 = qc * 64;
    if (q0 >= m) return;

    int tid = threadIdx.x, w = tid >> 5, lane = tid & 31;
    __shared__ float Ks[32][HD];
    __shared__ float Vs[32][HD];

    float q[8][4], acc[8][4], mx[8], l[8];
    int   tok[8];
    #pragma unroll
    for (int t = 0; t < 8; t++) {
        int qi = q0 + w * 8 + t;
        if (qi < m) {
            tok[t] = g_list[g * N_TOK + qi];
            float4 qv = *(const float4*)&g_qkv[(size_t)tok[t] * 3072 + h * HD + lane * 4];
            q[t][0] = qv.x; q[t][1] = qv.y; q[t][2] = qv.z; q[t][3] = qv.w;
        } else tok[t] = -1;
        mx[t] = -1e30f; l[t] = 0.f;
        acc[t][0] = acc[t][1] = acc[t][2] = acc[t][3] = 0.f;
    }

    int ntile = (m + 31) >> 5;
    for (int kt = 0; kt < ntile; kt++) {
        int kbase = kt * 32;
        #pragma unroll
        for (int it = 0; it < 4; it++) {
            int p  = tid + it * 256;
            int j  = p >> 5, c4 = p & 31;
            int kj = kbase + j;
            float4 kv = {0,0,0,0}, vv = {0,0,0,0};
            if (kj < m) {
                int ktok = g_list[g * N_TOK + kj];
                const float4* b4 = (const float4*)&g_qkv[(size_t)ktok * 3072];
                kv = b4[256 + h * 32 + c4];
                vv = b4[512 + h * 32 + c4];
            }
            *(float4*)&Ks[j][c4 * 4] = kv;
            *(float4*)&Vs[j][c4 * 4] = vv;
        }
        __syncthreads();

        int jmax = m - kbase; if (jmax > 32) jmax = 32;
        for (int j = 0; j < jmax; j++) {
            float4 kj4 = *(const float4*)&Ks[j][lane * 4];
            float4 vj4 = *(const float4*)&Vs[j][lane * 4];
            #pragma unroll
            for (int t = 0; t < 8; t++) {
                if (tok[t] < 0) continue;
                float s = q[t][0] * kj4.x + q[t][1] * kj4.y
                        + q[t][2] * kj4.z + q[t][3] * kj4.w;
                #pragma unroll
                for (int off = 16; off; off >>= 1) s += __shfl_xor_sync(0xffffffffu, s, off);
                s *= 0.08838834764831845f;
                if (s <= mx[t]) {
                    float p = __expf(s - mx[t]);
                    l[t] += p;
                    acc[t][0] += p * vj4.x; acc[t][1] += p * vj4.y;
                    acc[t][2] += p * vj4.z; acc[t][3] += p * vj4.w;
                } else {
                    float corr = __expf(mx[t] - s);
                    l[t] = l[t] * corr + 1.0f;
                    acc[t][0] = acc[t][0] * corr + vj4.x;
                    acc[t][1] = acc[t][1] * corr + vj4.y;
                    acc[t][2] = acc[t][2] * corr + vj4.z;
                    acc[t][3] = acc[t][3] * corr + vj4.w;
                    mx[t] = s;
                }
            }
        }
        __syncthreads();
    }

    #pragma unroll
    for (int t = 0; t < 8; t++) {
        if (tok[t] < 0) continue;
        float inv = 1.0f / l[t];
        float a[4] = { acc[t][0] * inv, acc[t][1] * inv, acc[t][2] * inv, acc[t][3] * inv };
        __half hs[4], ls[4];
        #pragma unroll
        for (int j = 0; j < 4; j++) {
            hs[j] = __float2half_rn(a[j]);
            ls[j] = __float2half_rn(a[j] - __half2float(hs[j]));
        }
        size_t idx = (size_t)tok[t] * C_DIM + h * HD + lane * 4;
        *(uint2*)&g_ah[idx] = *(uint2*)hs;
        *(uint2*)&g_al[idx] = *(uint2*)ls;
    }
}

// ---------------- 6) y = x + coef[n,c] (R4-proven simple version) ----------
__global__ void k_add(const float* __restrict__ x, float* __restrict__ y) {
    const float4* x4 = (const float4*)x;
    float4* y4 = (float4*)y;
    const int total = N_TOK * C_DIM * (HW / 4);   // 2^25 float4
    int stride = gridDim.x * blockDim.x;
    for (int i = blockIdx.x * blockDim.x + threadIdx.x; i < total; i += stride) {
        float c = g_coef[i >> 4];
        float4 v = x4[i];
        v.x += c; v.y += c; v.z += c; v.w += c;
        y4[i] = v;
    }
}

// ---------------- launch ---------------------------------------------------
extern "C" void kernel_launch(void* const* d_in, const int* in_sizes, int n_in,
                              void* d_out, int out_size) {
    const float* x          = (const float*)d_in[0];
    const int*   braw       = (const int*)  d_in[1];
    const float* ln_w       = (const float*)d_in[2];
    const float* ln_b       = (const float*)d_in[3];
    const float* in_proj_w  = (const float*)d_in[4];
    const float* in_proj_b  = (const float*)d_in[5];
    const float* out_proj_w = (const float*)d_in[6];
    const float* out_proj_b = (const float*)d_in[7];
    const float* gamma      = (const float*)d_in[8];
    float* y = (float*)d_out;

    __half *p_fh, *p_fl, *p_wq, *p_wo, *p_ah, *p_al;
    float *p_qkv, *p_coef;
    cudaGetSymbolAddress((void**)&p_fh,  g_fh);
    cudaGetSymbolAddress((void**)&p_fl,  g_fl);
    cudaGetSymbolAddress((void**)&p_wq,  g_wq);
    cudaGetSymbolAddress((void**)&p_wo,  g_wo);
    cudaGetSymbolAddress((void**)&p_ah,  g_ah);
    cudaGetSymbolAddress((void**)&p_al,  g_al);
    cudaGetSymbolAddress((void**)&p_qkv, g_qkv);
    cudaGetSymbolAddress((void**)&p_coef, g_coef);

    // Launch order arranged so k_mean sits in profiling slot #4.
    k_half   <<<3072, 256>>>(in_proj_w,  p_wq, 3 * C_DIM * C_DIM / 4);
    k_half   <<<1024, 256>>>(out_proj_w, p_wo, C_DIM * C_DIM / 4);
    k_groups <<<8, 256>>>(braw);
    k_mean   <<<1184, 256>>>(x);
    k_ln     <<<N_TOK, 256>>>(ln_w, ln_b);
    k_hgemm  <<<dim3(24, 16), 256>>>(p_fh, p_fl, p_wq, in_proj_b, p_qkv,
                                     3 * C_DIM, 0, nullptr);
    k_attn   <<<NHEAD * NGRP * QCH, 256>>>();
    k_hgemm  <<<dim3(8, 16), 256>>>(p_ah, p_al, p_wo, out_proj_b, p_coef,
                                    C_DIM, 1, gamma);
    k_add    <<<32768, 256>>>(x, y);
}

// round 9
// speedup vs baseline: 1.4667x; 1.1675x over previous
#include <cuda_runtime.h>
#include <cuda_fp16.h>
#include <stdint.h>
#include <math.h>

#define N_TOK 2048
#define C_DIM 1024
#define NHEAD 8
#define HD    128
#define NGRP  32
#define HW    64
#define PAD   40   // smem row stride in halfs (80B, multiple of 16B, conflict-free)

// ---------------- scratch (device globals: allocation-free) ----------------
__device__ float g_feat[N_TOK * C_DIM];
__device__ float g_qkv [N_TOK * 3 * C_DIM];
__device__ float g_coef[N_TOK * C_DIM];
__device__ int   g_bidx[N_TOK];
__device__ int   g_cnt [NGRP];
__device__ int   g_list[NGRP * N_TOK];
__device__ __half g_f  [N_TOK * C_DIM];          // LN output, fp16
__device__ __half g_wq [3 * C_DIM * C_DIM];
__device__ __half g_wo [C_DIM * C_DIM];
__device__ __half g_a  [N_TOK * C_DIM];          // attention output, fp16

__device__ __forceinline__ uint32_t smem_u32(const void* p) {
    uint32_t a;
    asm("{ .reg .u64 t; cvta.to.shared.u64 t, %1; cvt.u32.u64 %0, t; }" : "=r"(a) : "l"(p));
    return a;
}
__device__ __forceinline__ void cp16(uint32_t dst, const void* src) {
    asm volatile("cp.async.cg.shared.global [%0], [%1], 16;" :: "r"(dst), "l"(src));
}

// ---------------- 1) groups: detect width, lists + counts ------------------
__global__ void k_groups(const int* __restrict__ raw) {
    __shared__ int sb[N_TOK];
    __shared__ int s64;
    if (threadIdx.x == 0) {
        int acc = 0;
        #pragma unroll
        for (int i = 0; i < 32; i++) acc |= raw[2 * i + 1];
        s64 = (acc == 0);
    }
    __syncthreads();
    for (int i = threadIdx.x; i < N_TOK; i += blockDim.x)
        sb[i] = s64 ? raw[2 * i] : raw[i];
    __syncthreads();
    int i = blockIdx.x * blockDim.x + threadIdx.x;   // grid 8 x 256
    if (blockIdx.x == 0) {
        for (int j = threadIdx.x; j < N_TOK; j += blockDim.x) g_bidx[j] = sb[j];
    }
    int b = sb[i];
    int pos = 0;
    for (int j = 0; j < i; j++) pos += (sb[j] == b) ? 1 : 0;
    g_list[b * N_TOK + pos] = i;
    if (blockIdx.x == 0 && threadIdx.x < NGRP) {
        int c = 0;
        for (int j = 0; j < N_TOK; j++) c += (sb[j] == (int)threadIdx.x) ? 1 : 0;
        g_cnt[threadIdx.x] = c;
    }
}

// ---------------- 2) feat = mean over H*W (measured 81% of DRAM peak) ------
__global__ void k_mean(const float* __restrict__ x) {
    const float4* x4 = (const float4*)x;
    int gw    = (blockIdx.x * blockDim.x + threadIdx.x) >> 5;
    int lane  = threadIdx.x & 31;
    int nwarp = (gridDim.x * blockDim.x) >> 5;
    const int CHUNKS = N_TOK * C_DIM / 16;        // 131072 chunks of 16 rows
    for (int ch = gw; ch < CHUNKS; ch += nwarp) {
        size_t base = (size_t)ch * 256 + lane;
        float4 v[8];
        #pragma unroll
        for (int j = 0; j < 8; j++) v[j] = __ldcs(&x4[base + 32 * j]);
        float s[8];
        #pragma unroll
        for (int j = 0; j < 8; j++) s[j] = (v[j].x + v[j].y) + (v[j].z + v[j].w);
        #pragma unroll
        for (int j = 0; j < 8; j++) {
            s[j] += __shfl_xor_sync(0xffffffffu, s[j], 8);
            s[j] += __shfl_xor_sync(0xffffffffu, s[j], 4);
            s[j] += __shfl_xor_sync(0xffffffffu, s[j], 2);
            s[j] += __shfl_xor_sync(0xffffffffu, s[j], 1);
        }
        if (lane == 0 || lane == 16) {
            int r0 = ch * 16 + (lane >> 4);
            #pragma unroll
            for (int j = 0; j < 8; j++) g_feat[r0 + 2 * j] = s[j] * (1.0f / 64.0f);
        }
    }
}

// ---------------- 3) LayerNorm over C, emit fp16 ---------------------------
__global__ void k_ln(const float* __restrict__ w, const float* __restrict__ b) {
    int row = blockIdx.x, tid = threadIdx.x;
    int lane = tid & 31, warp = tid >> 5;
    float4 v = ((const float4*)g_feat)[row * 256 + tid];
    float s  = v.x + v.y + v.z + v.w;
    float sq = v.x * v.x + v.y * v.y + v.z * v.z + v.w * v.w;
    #pragma unroll
    for (int off = 16; off; off >>= 1) {
        s  += __shfl_xor_sync(0xffffffffu, s,  off);
        sq += __shfl_xor_sync(0xffffffffu, sq, off);
    }
    __shared__ float rs[8], rq[8];
    if (lane == 0) { rs[warp] = s; rq[warp] = sq; }
    __syncthreads();
    float S = 0.f, SQ = 0.f;
    #pragma unroll
    for (int i = 0; i < 8; i++) { S += rs[i]; SQ += rq[i]; }
    float mu   = S * (1.0f / C_DIM);
    float var  = SQ * (1.0f / C_DIM) - mu * mu;
    float rstd = rsqrtf(var + 1e-5f);
    float4 wv = ((const float4*)w)[tid], bv = ((const float4*)b)[tid];
    __half hs[4];
    hs[0] = __float2half_rn((v.x - mu) * rstd * wv.x + bv.x);
    hs[1] = __float2half_rn((v.y - mu) * rstd * wv.y + bv.y);
    hs[2] = __float2half_rn((v.z - mu) * rstd * wv.z + bv.z);
    hs[3] = __float2half_rn((v.w - mu) * rstd * wv.w + bv.w);
    *(uint2*)&g_f[row * C_DIM + tid * 4] = *(uint2*)hs;
}

// ---------------- 3b) fp32 -> fp16 (weights) -------------------------------
__global__ void k_half(const float* __restrict__ src, __half* __restrict__ dst, int n4) {
    int i = blockIdx.x * blockDim.x + threadIdx.x;
    if (i >= n4) return;
    float4 v = __ldcs(&((const float4*)src)[i]);
    __half hs[4] = { __float2half_rn(v.x), __float2half_rn(v.y),
                     __float2half_rn(v.z), __float2half_rn(v.w) };
    *(uint2*)&dst[i * 4] = *(uint2*)hs;
}

// ---------------- 4) HMMA GEMM, single fp16 term, cp.async 2-stage ---------
// C[M,N] = A[M,K] * B[N,K]^T + bias. Block 128x128, 8 warps, k-chunk 32.
__global__ void __launch_bounds__(256)
k_hgemm(const __half* __restrict__ A, const __half* __restrict__ B,
        const float* __restrict__ bias, float* __restrict__ C,
        int Ncols, int mode, const float* __restrict__ gamma) {
    __shared__ __align__(16) __half sA[2][128 * PAD];
    __shared__ __align__(16) __half sB[2][128 * PAD];

    const int tid = threadIdx.x, warp = tid >> 5, lane = tid & 31;
    const int wm = warp >> 2, wn = warp & 3;       // 2 x 4 warp grid
    const int bM = blockIdx.y * 128, bN = blockIdx.x * 128;

    float acc[4][4][4];
    #pragma unroll
    for (int i = 0; i < 4; i++)
        #pragma unroll
        for (int j = 0; j < 4; j++)
            #pragma unroll
            for (int c = 0; c < 4; c++) acc[i][j][c] = 0.f;

    const int lr = tid >> 2, lc = (tid & 3) * 8;   // rows 0-63 / +64 second pass

    const int a_row = lane & 15, a_k = (lane >> 4) * 8;
    const int b_row = (lane & 7) + ((lane >> 4) << 3);
    const int b_k   = ((lane >> 3) & 1) * 8;

    const uint32_t sA_b = smem_u32(sA), sB_b = smem_u32(sB);

    #define LOAD_STAGE(kc, st) do {                                           \
        uint32_t so = (uint32_t)(st) * (128 * PAD * 2);                       \
        size_t ga0 = (size_t)(bM + lr)      * C_DIM + (kc) * 32 + lc;         \
        size_t ga1 = (size_t)(bM + lr + 64) * C_DIM + (kc) * 32 + lc;         \
        size_t gb0 = (size_t)(bN + lr)      * C_DIM + (kc) * 32 + lc;         \
        size_t gb1 = (size_t)(bN + lr + 64) * C_DIM + (kc) * 32 + lc;         \
        cp16(sA_b + so + (lr * PAD + lc) * 2,        A + ga0);                \
        cp16(sA_b + so + ((lr + 64) * PAD + lc) * 2, A + ga1);                \
        cp16(sB_b + so + (lr * PAD + lc) * 2,        B + gb0);                \
        cp16(sB_b + so + ((lr + 64) * PAD + lc) * 2, B + gb1);                \
        asm volatile("cp.async.commit_group;");                               \
    } while (0)

    LOAD_STAGE(0, 0);

    for (int kc = 0; kc < 32; kc++) {
        int cur = kc & 1;
        if (kc < 31) {
            LOAD_STAGE(kc + 1, cur ^ 1);
            asm volatile("cp.async.wait_group 1;");
        } else {
            asm volatile("cp.async.wait_group 0;");
        }
        __syncthreads();

        uint32_t so = (uint32_t)cur * (128 * PAD * 2);
        #pragma unroll
        for (int ks = 0; ks < 32; ks += 16) {
            uint32_t aF[4][4], bF[4][2];
            #pragma unroll
            for (int i = 0; i < 4; i++) {
                uint32_t off = so + (uint32_t)((wm * 64 + i * 16 + a_row) * PAD + ks + a_k) * 2;
                asm volatile("ldmatrix.sync.aligned.m8n8.x4.shared.b16 {%0,%1,%2,%3}, [%4];"
                    : "=r"(aF[i][0]), "=r"(aF[i][1]), "=r"(aF[i][2]), "=r"(aF[i][3])
                    : "r"(sA_b + off));
            }
            #pragma unroll
            for (int jj = 0; jj < 2; jj++) {
                uint32_t off = so + (uint32_t)((wn * 32 + jj * 16 + b_row) * PAD + ks + b_k) * 2;
                uint32_t r0, r1, r2, r3;
                asm volatile("ldmatrix.sync.aligned.m8n8.x4.shared.b16 {%0,%1,%2,%3}, [%4];"
                    : "=r"(r0), "=r"(r1), "=r"(r2), "=r"(r3) : "r"(sB_b + off));
                bF[jj * 2 + 0][0] = r0; bF[jj * 2 + 0][1] = r1;
                bF[jj * 2 + 1][0] = r2; bF[jj * 2 + 1][1] = r3;
            }
            #pragma unroll
            for (int i = 0; i < 4; i++)
                #pragma unroll
                for (int j = 0; j < 4; j++) {
                    asm volatile(
                        "mma.sync.aligned.m16n8k16.row.col.f32.f16.f16.f32 "
                        "{%0,%1,%2,%3}, {%4,%5,%6,%7}, {%8,%9}, {%0,%1,%2,%3};"
                        : "+f"(acc[i][j][0]), "+f"(acc[i][j][1]),
                          "+f"(acc[i][j][2]), "+f"(acc[i][j][3])
                        : "r"(aF[i][0]), "r"(aF[i][1]), "r"(aF[i][2]), "r"(aF[i][3]),
                          "r"(bF[j][0]), "r"(bF[j][1]));
                }
        }
        __syncthreads();
    }

    const int g4 = lane >> 2, t4 = lane & 3;
    #pragma unroll
    for (int i = 0; i < 4; i++) {
        int r0 = bM + wm * 64 + i * 16 + g4;
        int r1 = r0 + 8;
        float gm0 = 1.f, gm1 = 1.f;
        if (mode == 1) {
            gm0 = (g_cnt[g_bidx[r0]] > 1) ? gamma[0] : 0.0f;
            gm1 = (g_cnt[g_bidx[r1]] > 1) ? gamma[0] : 0.0f;
        }
        #pragma unroll
        for (int j = 0; j < 4; j++) {
            int c = bN + wn * 32 + j * 8 + 2 * t4;
            float b0 = bias[c], b1 = bias[c + 1];
            float2 o0 = { (acc[i][j][0] + b0) * gm0, (acc[i][j][1] + b1) * gm0 };
            float2 o1 = { (acc[i][j][2] + b0) * gm1, (acc[i][j][3] + b1) * gm1 };
            *(float2*)&C[(size_t)r0 * Ncols + c] = o0;
            *(float2*)&C[(size_t)r1 * Ncols + c] = o1;
        }
    }
}

// ---------------- 5) per-(head,group) flash attention (R4-proven) ----------
#define QCH 32
__global__ void k_attn() {
    int bx = blockIdx.x;
    int qc = bx & (QCH - 1);
    int g  = (bx >> 5) & (NGRP - 1);
    int h  = bx >> 10;
    int m  = g_cnt[g];
    int q0 = qc * 64;
    if (q0 >= m) return;

    int tid = threadIdx.x, w = tid >> 5, lane = tid & 31;
    __shared__ float Ks[32][HD];
    __shared__ float Vs[32][HD];

    float q[8][4], acc[8][4], mx[8], l[8];
    int   tok[8];
    #pragma unroll
    for (int t = 0; t < 8; t++) {
        int qi = q0 + w * 8 + t;
        if (qi < m) {
            tok[t] = g_list[g * N_TOK + qi];
            float4 qv = *(const float4*)&g_qkv[(size_t)tok[t] * 3072 + h * HD + lane * 4];
            q[t][0] = qv.x; q[t][1] = qv.y; q[t][2] = qv.z; q[t][3] = qv.w;
        } else tok[t] = -1;
        mx[t] = -1e30f; l[t] = 0.f;
        acc[t][0] = acc[t][1] = acc[t][2] = acc[t][3] = 0.f;
    }

    int ntile = (m + 31) >> 5;
    for (int kt = 0; kt < ntile; kt++) {
        int kbase = kt * 32;
        #pragma unroll
        for (int it = 0; it < 4; it++) {
            int p  = tid + it * 256;
            int j  = p >> 5, c4 = p & 31;
            int kj = kbase + j;
            float4 kv = {0,0,0,0}, vv = {0,0,0,0};
            if (kj < m) {
                int ktok = g_list[g * N_TOK + kj];
                const float4* b4 = (const float4*)&g_qkv[(size_t)ktok * 3072];
                kv = b4[256 + h * 32 + c4];
                vv = b4[512 + h * 32 + c4];
            }
            *(float4*)&Ks[j][c4 * 4] = kv;
            *(float4*)&Vs[j][c4 * 4] = vv;
        }
        __syncthreads();

        int jmax = m - kbase; if (jmax > 32) jmax = 32;
        for (int j = 0; j < jmax; j++) {
            float4 kj4 = *(const float4*)&Ks[j][lane * 4];
            float4 vj4 = *(const float4*)&Vs[j][lane * 4];
            #pragma unroll
            for (int t = 0; t < 8; t++) {
                if (tok[t] < 0) continue;
                float s = q[t][0] * kj4.x + q[t][1] * kj4.y
                        + q[t][2] * kj4.z + q[t][3] * kj4.w;
                #pragma unroll
                for (int off = 16; off; off >>= 1) s += __shfl_xor_sync(0xffffffffu, s, off);
                s *= 0.08838834764831845f;
                if (s <= mx[t]) {
                    float p = __expf(s - mx[t]);
                    l[t] += p;
                    acc[t][0] += p * vj4.x; acc[t][1] += p * vj4.y;
                    acc[t][2] += p * vj4.z; acc[t][3] += p * vj4.w;
                } else {
                    float corr = __expf(mx[t] - s);
                    l[t] = l[t] * corr + 1.0f;
                    acc[t][0] = acc[t][0] * corr + vj4.x;
                    acc[t][1] = acc[t][1] * corr + vj4.y;
                    acc[t][2] = acc[t][2] * corr + vj4.z;
                    acc[t][3] = acc[t][3] * corr + vj4.w;
                    mx[t] = s;
                }
            }
        }
        __syncthreads();
    }

    #pragma unroll
    for (int t = 0; t < 8; t++) {
        if (tok[t] < 0) continue;
        float inv = 1.0f / l[t];
        __half hs[4];
        hs[0] = __float2half_rn(acc[t][0] * inv);
        hs[1] = __float2half_rn(acc[t][1] * inv);
        hs[2] = __float2half_rn(acc[t][2] * inv);
        hs[3] = __float2half_rn(acc[t][3] * inv);
        *(uint2*)&g_a[(size_t)tok[t] * C_DIM + h * HD + lane * 4] = *(uint2*)hs;
    }
}

// ---------------- 6) y = x + coef[n,c] (R4-proven simple version) ----------
__global__ void k_add(const float* __restrict__ x, float* __restrict__ y) {
    const float4* x4 = (const float4*)x;
    float4* y4 = (float4*)y;
    const int total = N_TOK * C_DIM * (HW / 4);   // 2^25 float4
    int stride = gridDim.x * blockDim.x;
    for (int i = blockIdx.x * blockDim.x + threadIdx.x; i < total; i += stride) {
        float c = g_coef[i >> 4];
        float4 v = x4[i];
        v.x += c; v.y += c; v.z += c; v.w += c;
        y4[i] = v;
    }
}

// ---------------- launch ---------------------------------------------------
extern "C" void kernel_launch(void* const* d_in, const int* in_sizes, int n_in,
                              void* d_out, int out_size) {
    const float* x          = (const float*)d_in[0];
    const int*   braw       = (const int*)  d_in[1];
    const float* ln_w       = (const float*)d_in[2];
    const float* ln_b       = (const float*)d_in[3];
    const float* in_proj_w  = (const float*)d_in[4];
    const float* in_proj_b  = (const float*)d_in[5];
    const float* out_proj_w = (const float*)d_in[6];
    const float* out_proj_b = (const float*)d_in[7];
    const float* gamma      = (const float*)d_in[8];
    float* y = (float*)d_out;

    __half *p_f, *p_wq, *p_wo, *p_a;
    float *p_qkv, *p_coef;
    cudaGetSymbolAddress((void**)&p_f,   g_f);
    cudaGetSymbolAddress((void**)&p_wq,  g_wq);
    cudaGetSymbolAddress((void**)&p_wo,  g_wo);
    cudaGetSymbolAddress((void**)&p_a,   g_a);
    cudaGetSymbolAddress((void**)&p_qkv, g_qkv);
    cudaGetSymbolAddress((void**)&p_coef, g_coef);

    // Launch order arranged so the QKV GEMM sits in profiling slot #4.
    k_half   <<<3072, 256>>>(in_proj_w,  p_wq, 3 * C_DIM * C_DIM / 4);
    k_mean   <<<1184, 256>>>(x);
    k_ln     <<<N_TOK, 256>>>(ln_w, ln_b);
    k_hgemm  <<<dim3(24, 16), 256>>>(p_f, p_wq, in_proj_b, p_qkv,
                                     3 * C_DIM, 0, nullptr);
    k_groups <<<8, 256>>>(braw);
    k_half   <<<1024, 256>>>(out_proj_w, p_wo, C_DIM * C_DIM / 4);
    k_attn   <<<NHEAD * NGRP * QCH, 256>>>();
    k_hgemm  <<<dim3(8, 16), 256>>>(p_a, p_wo, out_proj_b, p_coef,
                                    C_DIM, 1, gamma);
    k_add    <<<32768, 256>>>(x, y);
}

// round 10
// speedup vs baseline: 2.0393x; 1.3904x over previous
#include <cuda_runtime.h>
#include <cuda_fp16.h>
#include <stdint.h>
#include <math.h>

#define N_TOK 2048
#define C_DIM 1024
#define NHEAD 8
#define HD    128
#define NGRP  32
#define HW    64
#define PAD   40    // GEMM smem stride (halfs)
#define ATS   136   // attention smem stride (halfs), 272B: 16B-aligned, conflict-free

// ---------------- scratch ----------------------------------------------------
__device__ float g_feat[N_TOK * C_DIM];
__device__ float g_coef[N_TOK * C_DIM];
__device__ int   g_bidx[N_TOK];
__device__ int   g_cnt [NGRP];
__device__ int   g_list[NGRP * N_TOK];
__device__ __half g_f   [N_TOK * C_DIM];
__device__ __half g_qkvh[N_TOK * 3 * C_DIM];
__device__ __half g_wq  [3 * C_DIM * C_DIM];
__device__ __half g_wo  [C_DIM * C_DIM];
__device__ __half g_a   [N_TOK * C_DIM];

__device__ __forceinline__ uint32_t smem_u32(const void* p) {
    uint32_t a;
    asm("{ .reg .u64 t; cvta.to.shared.u64 t, %1; cvt.u32.u64 %0, t; }" : "=r"(a) : "l"(p));
    return a;
}
__device__ __forceinline__ void cp16(uint32_t dst, const void* src) {
    asm volatile("cp.async.cg.shared.global [%0], [%1], 16;" :: "r"(dst), "l"(src));
}
#define MMA16816(d, a, b)                                                       \
    asm volatile("mma.sync.aligned.m16n8k16.row.col.f32.f16.f16.f32 "           \
        "{%0,%1,%2,%3}, {%4,%5,%6,%7}, {%8,%9}, {%0,%1,%2,%3};"                 \
        : "+f"((d)[0]), "+f"((d)[1]), "+f"((d)[2]), "+f"((d)[3])                \
        : "r"((a)[0]), "r"((a)[1]), "r"((a)[2]), "r"((a)[3]),                   \
          "r"((b)[0]), "r"((b)[1]))
#define LDSM4(r, addr)                                                          \
    asm volatile("ldmatrix.sync.aligned.m8n8.x4.shared.b16 {%0,%1,%2,%3}, [%4];"\
        : "=r"((r)[0]), "=r"((r)[1]), "=r"((r)[2]), "=r"((r)[3]) : "r"(addr))
#define LDSM4T(r, addr)                                                         \
    asm volatile("ldmatrix.sync.aligned.m8n8.x4.trans.shared.b16 {%0,%1,%2,%3}, [%4];"\
        : "=r"((r)[0]), "=r"((r)[1]), "=r"((r)[2]), "=r"((r)[3]) : "r"(addr))

// ---------------- 1) groups --------------------------------------------------
__global__ void k_groups(const int* __restrict__ raw) {
    __shared__ int sb[N_TOK];
    __shared__ int s64;
    if (threadIdx.x == 0) {
        int acc = 0;
        #pragma unroll
        for (int i = 0; i < 32; i++) acc |= raw[2 * i + 1];
        s64 = (acc == 0);
    }
    __syncthreads();
    for (int i = threadIdx.x; i < N_TOK; i += blockDim.x)
        sb[i] = s64 ? raw[2 * i] : raw[i];
    __syncthreads();
    int i = blockIdx.x * blockDim.x + threadIdx.x;
    if (blockIdx.x == 0) {
        for (int j = threadIdx.x; j < N_TOK; j += blockDim.x) g_bidx[j] = sb[j];
    }
    int b = sb[i];
    int pos = 0;
    for (int j = 0; j < i; j++) pos += (sb[j] == b) ? 1 : 0;
    g_list[b * N_TOK + pos] = i;
    if (blockIdx.x == 0 && threadIdx.x < NGRP) {
        int c = 0;
        for (int j = 0; j < N_TOK; j++) c += (sb[j] == (int)threadIdx.x) ? 1 : 0;
        g_cnt[threadIdx.x] = c;
    }
}

// ---------------- 2) feat = mean over H*W (measured 81% DRAM peak) ----------
__global__ void k_mean(const float* __restrict__ x) {
    const float4* x4 = (const float4*)x;
    int gw    = (blockIdx.x * blockDim.x + threadIdx.x) >> 5;
    int lane  = threadIdx.x & 31;
    int nwarp = (gridDim.x * blockDim.x) >> 5;
    const int CHUNKS = N_TOK * C_DIM / 16;
    for (int ch = gw; ch < CHUNKS; ch += nwarp) {
        size_t base = (size_t)ch * 256 + lane;
        float4 v[8];
        #pragma unroll
        for (int j = 0; j < 8; j++) v[j] = __ldcs(&x4[base + 32 * j]);
        float s[8];
        #pragma unroll
        for (int j = 0; j < 8; j++) s[j] = (v[j].x + v[j].y) + (v[j].z + v[j].w);
        #pragma unroll
        for (int j = 0; j < 8; j++) {
            s[j] += __shfl_xor_sync(0xffffffffu, s[j], 8);
            s[j] += __shfl_xor_sync(0xffffffffu, s[j], 4);
            s[j] += __shfl_xor_sync(0xffffffffu, s[j], 2);
            s[j] += __shfl_xor_sync(0xffffffffu, s[j], 1);
        }
        if (lane == 0 || lane == 16) {
            int r0 = ch * 16 + (lane >> 4);
            #pragma unroll
            for (int j = 0; j < 8; j++) g_feat[r0 + 2 * j] = s[j] * (1.0f / 64.0f);
        }
    }
}

// ---------------- 3) LayerNorm, emit fp16 ------------------------------------
__global__ void k_ln(const float* __restrict__ w, const float* __restrict__ b) {
    int row = blockIdx.x, tid = threadIdx.x;
    int lane = tid & 31, warp = tid >> 5;
    float4 v = ((const float4*)g_feat)[row * 256 + tid];
    float s  = v.x + v.y + v.z + v.w;
    float sq = v.x * v.x + v.y * v.y + v.z * v.z + v.w * v.w;
    #pragma unroll
    for (int off = 16; off; off >>= 1) {
        s  += __shfl_xor_sync(0xffffffffu, s,  off);
        sq += __shfl_xor_sync(0xffffffffu, sq, off);
    }
    __shared__ float rs[8], rq[8];
    if (lane == 0) { rs[warp] = s; rq[warp] = sq; }
    __syncthreads();
    float S = 0.f, SQ = 0.f;
    #pragma unroll
    for (int i = 0; i < 8; i++) { S += rs[i]; SQ += rq[i]; }
    float mu   = S * (1.0f / C_DIM);
    float var  = SQ * (1.0f / C_DIM) - mu * mu;
    float rstd = rsqrtf(var + 1e-5f);
    float4 wv = ((const float4*)w)[tid], bv = ((const float4*)b)[tid];
    __half hs[4];
    hs[0] = __float2half_rn((v.x - mu) * rstd * wv.x + bv.x);
    hs[1] = __float2half_rn((v.y - mu) * rstd * wv.y + bv.y);
    hs[2] = __float2half_rn((v.z - mu) * rstd * wv.z + bv.z);
    hs[3] = __float2half_rn((v.w - mu) * rstd * wv.w + bv.w);
    *(uint2*)&g_f[row * C_DIM + tid * 4] = *(uint2*)hs;
}

// ---------------- 3b) fp32 -> fp16 (weights) ---------------------------------
__global__ void k_half(const float* __restrict__ src, __half* __restrict__ dst, int n4) {
    int i = blockIdx.x * blockDim.x + threadIdx.x;
    if (i >= n4) return;
    float4 v = __ldcs(&((const float4*)src)[i]);
    __half hs[4] = { __float2half_rn(v.x), __float2half_rn(v.y),
                     __float2half_rn(v.z), __float2half_rn(v.w) };
    *(uint2*)&dst[i * 4] = *(uint2*)hs;
}

// ---------------- 4) HMMA GEMM, cp.async 2-stage -----------------------------
// mode 0: write fp16 to Ch. mode 1: write fp32 coef = valid?gamma*(acc+b):0.
__global__ void __launch_bounds__(256)
k_hgemm(const __half* __restrict__ A, const __half* __restrict__ B,
        const float* __restrict__ bias, float* __restrict__ Cf, __half* __restrict__ Ch,
        int Ncols, int mode, const float* __restrict__ gamma) {
    __shared__ __align__(16) __half sA[2][128 * PAD];
    __shared__ __align__(16) __half sB[2][128 * PAD];

    const int tid = threadIdx.x, warp = tid >> 5, lane = tid & 31;
    const int wm = warp >> 2, wn = warp & 3;
    const int bM = blockIdx.y * 128, bN = blockIdx.x * 128;

    float acc[4][4][4];
    #pragma unroll
    for (int i = 0; i < 4; i++)
        #pragma unroll
        for (int j = 0; j < 4; j++)
            #pragma unroll
            for (int c = 0; c < 4; c++) acc[i][j][c] = 0.f;

    const int lr = tid >> 2, lc = (tid & 3) * 8;
    const int a_row = lane & 15, a_k = (lane >> 4) * 8;
    const int b_row = (lane & 7) + ((lane >> 4) << 3);
    const int b_k   = ((lane >> 3) & 1) * 8;
    const uint32_t sA_b = smem_u32(sA), sB_b = smem_u32(sB);

    #define LOAD_STAGE(kc, st) do {                                           \
        uint32_t so = (uint32_t)(st) * (128 * PAD * 2);                       \
        size_t ga0 = (size_t)(bM + lr)      * C_DIM + (kc) * 32 + lc;         \
        size_t ga1 = (size_t)(bM + lr + 64) * C_DIM + (kc) * 32 + lc;         \
        size_t gb0 = (size_t)(bN + lr)      * C_DIM + (kc) * 32 + lc;         \
        size_t gb1 = (size_t)(bN + lr + 64) * C_DIM + (kc) * 32 + lc;         \
        cp16(sA_b + so + (lr * PAD + lc) * 2,        A + ga0);                \
        cp16(sA_b + so + ((lr + 64) * PAD + lc) * 2, A + ga1);                \
        cp16(sB_b + so + (lr * PAD + lc) * 2,        B + gb0);                \
        cp16(sB_b + so + ((lr + 64) * PAD + lc) * 2, B + gb1);                \
        asm volatile("cp.async.commit_group;");                               \
    } while (0)

    LOAD_STAGE(0, 0);
    for (int kc = 0; kc < 32; kc++) {
        int cur = kc & 1;
        if (kc < 31) {
            LOAD_STAGE(kc + 1, cur ^ 1);
            asm volatile("cp.async.wait_group 1;");
        } else {
            asm volatile("cp.async.wait_group 0;");
        }
        __syncthreads();
        uint32_t so = (uint32_t)cur * (128 * PAD * 2);
        #pragma unroll
        for (int ks = 0; ks < 32; ks += 16) {
            uint32_t aF[4][4], bF[4][2];
            #pragma unroll
            for (int i = 0; i < 4; i++) {
                uint32_t off = so + (uint32_t)((wm * 64 + i * 16 + a_row) * PAD + ks + a_k) * 2;
                LDSM4(aF[i], sA_b + off);
            }
            #pragma unroll
            for (int jj = 0; jj < 2; jj++) {
                uint32_t off = so + (uint32_t)((wn * 32 + jj * 16 + b_row) * PAD + ks + b_k) * 2;
                uint32_t r[4];
                LDSM4(r, sB_b + off);
                bF[jj * 2 + 0][0] = r[0]; bF[jj * 2 + 0][1] = r[1];
                bF[jj * 2 + 1][0] = r[2]; bF[jj * 2 + 1][1] = r[3];
            }
            #pragma unroll
            for (int i = 0; i < 4; i++)
                #pragma unroll
                for (int j = 0; j < 4; j++)
                    MMA16816(acc[i][j], aF[i], bF[j]);
        }
        __syncthreads();
    }

    const int g4 = lane >> 2, t4 = lane & 3;
    #pragma unroll
    for (int i = 0; i < 4; i++) {
        int r0 = bM + wm * 64 + i * 16 + g4;
        int r1 = r0 + 8;
        float gm0 = 1.f, gm1 = 1.f;
        if (mode == 1) {
            gm0 = (g_cnt[g_bidx[r0]] > 1) ? gamma[0] : 0.0f;
            gm1 = (g_cnt[g_bidx[r1]] > 1) ? gamma[0] : 0.0f;
        }
        #pragma unroll
        for (int j = 0; j < 4; j++) {
            int c = bN + wn * 32 + j * 8 + 2 * t4;
            float b0 = bias[c], b1 = bias[c + 1];
            if (mode == 1) {
                float2 o0 = { (acc[i][j][0] + b0) * gm0, (acc[i][j][1] + b1) * gm0 };
                float2 o1 = { (acc[i][j][2] + b0) * gm1, (acc[i][j][3] + b1) * gm1 };
                *(float2*)&Cf[(size_t)r0 * Ncols + c] = o0;
                *(float2*)&Cf[(size_t)r1 * Ncols + c] = o1;
            } else {
                __half h0[2] = { __float2half_rn(acc[i][j][0] + b0),
                                 __float2half_rn(acc[i][j][1] + b1) };
                __half h1[2] = { __float2half_rn(acc[i][j][2] + b0),
                                 __float2half_rn(acc[i][j][3] + b1) };
                *(uint32_t*)&Ch[(size_t)r0 * Ncols + c] = *(uint32_t*)h0;
                *(uint32_t*)&Ch[(size_t)r1 * Ncols + c] = *(uint32_t*)h1;
            }
        }
    }
}

// ---------------- 5) flash attention with HMMA -------------------------------
// Block: 128 threads (4 warps), one 64-query chunk of one (head, group).
#define QCH 32
__global__ void __launch_bounds__(128) k_attn() {
    int bx = blockIdx.x;
    int qc = bx & (QCH - 1);
    int g  = (bx >> 5) & (NGRP - 1);
    int h  = bx >> 10;
    int m  = g_cnt[g];
    int q0 = qc * 64;
    if (q0 >= m) return;

    int tid = threadIdx.x, w = tid >> 5, lane = tid & 31;
    __shared__ __align__(16) __half Qs[64 * ATS];
    __shared__ __align__(16) __half Ks[32 * ATS];
    __shared__ __align__(16) __half Vs[32 * ATS];
    const uint32_t qs_b = smem_u32(Qs), ks_b = smem_u32(Ks), vs_b = smem_u32(Vs);

    // ---- load Q tile (64 x 128 halfs), zero-filled beyond m ----
    #pragma unroll
    for (int it = 0; it < 8; it++) {
        int p = tid + it * 128;           // 1024 uint4 slots
        int r = p >> 4, c = p & 15;
        int qi = q0 + r;
        uint4 v = {0, 0, 0, 0};
        if (qi < m) {
            int tok = g_list[g * N_TOK + qi];
            v = *(const uint4*)&g_qkvh[(size_t)tok * 3072 + h * HD + c * 8];
        }
        *(uint4*)&Qs[r * ATS + c * 8] = v;
    }
    __syncthreads();

    // ---- preload Q fragments: warp w rows w*16..w*16+15, 8 k-steps ----
    const int a_row = lane & 15, a_k = (lane >> 4) * 8;
    uint32_t qf[8][4];
    #pragma unroll
    for (int ks = 0; ks < 8; ks++) {
        uint32_t off = (uint32_t)((w * 16 + a_row) * ATS + ks * 16 + a_k) * 2;
        LDSM4(qf[ks], qs_b + off);
    }

    float o[16][4];
    #pragma unroll
    for (int n = 0; n < 16; n++) { o[n][0] = o[n][1] = o[n][2] = o[n][3] = 0.f; }
    float mx0 = -1e30f, mx1 = -1e30f, l0 = 0.f, l1 = 0.f;

    const int b_row = (lane & 7) + ((lane >> 4) << 3);
    const int b_k   = ((lane >> 3) & 1) * 8;
    const int vrow  = (lane & 7) + ((lane >> 3) & 1) * 8;
    const int vcol  = (lane >> 4) * 8;
    const float SC  = 0.08838834764831845f;

    for (int kbase = 0; kbase < m; kbase += 32) {
        __syncthreads();   // previous tile's mma reads done
        // ---- load K,V tile (32 keys x 128 halfs each) ----
        #pragma unroll
        for (int it = 0; it < 8; it++) {
            int p = tid + it * 128;       // 1024 slots: 512 K, 512 V
            int isV = p >> 9;
            int q = p & 511;
            int r = q >> 4, c = q & 15;
            int kj = kbase + r;
            uint4 v = {0, 0, 0, 0};
            if (kj < m) {
                int tok = g_list[g * N_TOK + kj];
                v = *(const uint4*)&g_qkvh[(size_t)tok * 3072 + (1 + isV) * C_DIM + h * HD + c * 8];
            }
            if (isV) *(uint4*)&Vs[r * ATS + c * 8] = v;
            else     *(uint4*)&Ks[r * ATS + c * 8] = v;
        }
        __syncthreads();

        // ---- S = Q K^T : 4 n8-tiles (32 keys) ----
        float s[4][4];
        #pragma unroll
        for (int T = 0; T < 4; T++) { s[T][0] = s[T][1] = s[T][2] = s[T][3] = 0.f; }
        #pragma unroll
        for (int ks = 0; ks < 8; ks++) {
            uint32_t r0[4], r1[4];
            LDSM4(r0, ks_b + (uint32_t)((0  + b_row) * ATS + ks * 16 + b_k) * 2);
            LDSM4(r1, ks_b + (uint32_t)((16 + b_row) * ATS + ks * 16 + b_k) * 2);
            uint32_t bA[2] = { r0[0], r0[1] }, bB[2] = { r0[2], r0[3] };
            uint32_t bC[2] = { r1[0], r1[1] }, bD[2] = { r1[2], r1[3] };
            MMA16816(s[0], qf[ks], bA);
            MMA16816(s[1], qf[ks], bB);
            MMA16816(s[2], qf[ks], bC);
            MMA16816(s[3], qf[ks], bD);
        }

        // ---- scale + mask ----
        int cbase = kbase + 2 * (lane & 3);
        #pragma unroll
        for (int T = 0; T < 4; T++) {
            int k0 = cbase + T * 8;
            s[T][0] = (k0     < m) ? s[T][0] * SC : -1e30f;
            s[T][1] = (k0 + 1 < m) ? s[T][1] * SC : -1e30f;
            s[T][2] = (k0     < m) ? s[T][2] * SC : -1e30f;
            s[T][3] = (k0 + 1 < m) ? s[T][3] * SC : -1e30f;
        }

        // ---- row max (2 rows per lane) ----
        float m0 = s[0][0], m1 = s[0][2];
        #pragma unroll
        for (int T = 0; T < 4; T++) {
            m0 = fmaxf(m0, fmaxf(s[T][0], s[T][1]));
            m1 = fmaxf(m1, fmaxf(s[T][2], s[T][3]));
        }
        m0 = fmaxf(m0, __shfl_xor_sync(0xffffffffu, m0, 1));
        m0 = fmaxf(m0, __shfl_xor_sync(0xffffffffu, m0, 2));
        m1 = fmaxf(m1, __shfl_xor_sync(0xffffffffu, m1, 1));
        m1 = fmaxf(m1, __shfl_xor_sync(0xffffffffu, m1, 2));
        float mn0 = fmaxf(mx0, m0), mn1 = fmaxf(mx1, m1);
        float c0 = __expf(mx0 - mn0), c1 = __expf(mx1 - mn1);

        // ---- exp + row sum + P fragments ----
        float p[4][4];
        float s0 = 0.f, s1 = 0.f;
        #pragma unroll
        for (int T = 0; T < 4; T++) {
            p[T][0] = __expf(s[T][0] - mn0);
            p[T][1] = __expf(s[T][1] - mn0);
            p[T][2] = __expf(s[T][2] - mn1);
            p[T][3] = __expf(s[T][3] - mn1);
            s0 += p[T][0] + p[T][1];
            s1 += p[T][2] + p[T][3];
        }
        s0 += __shfl_xor_sync(0xffffffffu, s0, 1);
        s0 += __shfl_xor_sync(0xffffffffu, s0, 2);
        s1 += __shfl_xor_sync(0xffffffffu, s1, 1);
        s1 += __shfl_xor_sync(0xffffffffu, s1, 2);
        l0 = l0 * c0 + s0;
        l1 = l1 * c1 + s1;
        mx0 = mn0; mx1 = mn1;

        #pragma unroll
        for (int n = 0; n < 16; n++) {
            o[n][0] *= c0; o[n][1] *= c0; o[n][2] *= c1; o[n][3] *= c1;
        }

        // P accumulator fragments -> A operand fragments (FA-2 layout identity)
        uint32_t pf[2][4];
        #pragma unroll
        for (int kst = 0; kst < 2; kst++) {
            int T0 = kst * 2;
            __half2 h0 = __floats2half2_rn(p[T0][0],     p[T0][1]);
            __half2 h1 = __floats2half2_rn(p[T0][2],     p[T0][3]);
            __half2 h2 = __floats2half2_rn(p[T0 + 1][0], p[T0 + 1][1]);
            __half2 h3 = __floats2half2_rn(p[T0 + 1][2], p[T0 + 1][3]);
            pf[kst][0] = *(uint32_t*)&h0;
            pf[kst][1] = *(uint32_t*)&h1;
            pf[kst][2] = *(uint32_t*)&h2;
            pf[kst][3] = *(uint32_t*)&h3;
        }

        // ---- O += P V : V^T fragments via ldmatrix.trans ----
        #pragma unroll
        for (int kst = 0; kst < 2; kst++) {
            #pragma unroll
            for (int dt = 0; dt < 8; dt++) {
                uint32_t r[4];
                LDSM4T(r, vs_b + (uint32_t)((kst * 16 + vrow) * ATS + dt * 16 + vcol) * 2);
                uint32_t bA[2] = { r[0], r[1] }, bB[2] = { r[2], r[3] };
                MMA16816(o[dt * 2],     pf[kst], bA);
                MMA16816(o[dt * 2 + 1], pf[kst], bB);
            }
        }
    }

    // ---- normalize + write ----
    float inv0 = 1.0f / l0, inv1 = 1.0f / l1;
    int qi0 = q0 + w * 16 + (lane >> 2);
    int qi1 = qi0 + 8;
    int tok0 = (qi0 < m) ? g_list[g * N_TOK + qi0] : -1;
    int tok1 = (qi1 < m) ? g_list[g * N_TOK + qi1] : -1;
    int colb = h * HD + 2 * (lane & 3);
    #pragma unroll
    for (int dt = 0; dt < 16; dt++) {
        if (tok0 >= 0) {
            __half2 hv = __floats2half2_rn(o[dt][0] * inv0, o[dt][1] * inv0);
            *(uint32_t*)&g_a[(size_t)tok0 * C_DIM + colb + dt * 8] = *(uint32_t*)&hv;
        }
        if (tok1 >= 0) {
            __half2 hv = __floats2half2_rn(o[dt][2] * inv1, o[dt][3] * inv1);
            *(uint32_t*)&g_a[(size_t)tok1 * C_DIM + colb + dt * 8] = *(uint32_t*)&hv;
        }
    }
}

// ---------------- 6) y = x + coef[n,c] ---------------------------------------
__global__ void k_add(const float* __restrict__ x, float* __restrict__ y) {
    const float4* x4 = (const float4*)x;
    float4* y4 = (float4*)y;
    const int total = N_TOK * C_DIM * (HW / 4);
    int stride = gridDim.x * blockDim.x;
    for (int i = blockIdx.x * blockDim.x + threadIdx.x; i < total; i += stride) {
        float c = g_coef[i >> 4];
        float4 v = x4[i];
        v.x += c; v.y += c; v.z += c; v.w += c;
        y4[i] = v;
    }
}

// ---------------- launch ------------------------------------------------------
extern "C" void kernel_launch(void* const* d_in, const int* in_sizes, int n_in,
                              void* d_out, int out_size) {
    const float* x          = (const float*)d_in[0];
    const int*   braw       = (const int*)  d_in[1];
    const float* ln_w       = (const float*)d_in[2];
    const float* ln_b       = (const float*)d_in[3];
    const float* in_proj_w  = (const float*)d_in[4];
    const float* in_proj_b  = (const float*)d_in[5];
    const float* out_proj_w = (const float*)d_in[6];
    const float* out_proj_b = (const float*)d_in[7];
    const float* gamma      = (const float*)d_in[8];
    float* y = (float*)d_out;

    __half *p_f, *p_wq, *p_wo, *p_a, *p_qkvh;
    float *p_coef;
    cudaGetSymbolAddress((void**)&p_f,    g_f);
    cudaGetSymbolAddress((void**)&p_wq,   g_wq);
    cudaGetSymbolAddress((void**)&p_wo,   g_wo);
    cudaGetSymbolAddress((void**)&p_a,    g_a);
    cudaGetSymbolAddress((void**)&p_qkvh, g_qkvh);
    cudaGetSymbolAddress((void**)&p_coef, g_coef);

    // slot 4 (ncu) = QKV GEMM
    k_half   <<<3072, 256>>>(in_proj_w,  p_wq, 3 * C_DIM * C_DIM / 4);
    k_mean   <<<1184, 256>>>(x);
    k_ln     <<<N_TOK, 256>>>(ln_w, ln_b);
    k_hgemm  <<<dim3(24, 16), 256>>>(p_f, p_wq, in_proj_b, nullptr, p_qkvh,
                                     3 * C_DIM, 0, nullptr);
    k_groups <<<8, 256>>>(braw);
    k_half   <<<1024, 256>>>(out_proj_w, p_wo, C_DIM * C_DIM / 4);
    k_attn   <<<NHEAD * NGRP * QCH, 128>>>();
    k_hgemm  <<<dim3(8, 16), 256>>>(p_a, p_wo, out_proj_b, p_coef, nullptr,
                                    C_DIM, 1, gamma);
    k_add    <<<32768, 256>>>(x, y);
}